// round 3
// baseline (speedup 1.0000x reference)
#include <cuda_runtime.h>
#include <cuda_bf16.h>
#include <math.h>

#define NODES 50000
#define DF 64
#define HF 64
#define BN_EPS 1e-3f

typedef unsigned long long ull;

// ---------------- device scratch (static, no allocs) ----------------
__device__ float g_Wm1[DF * HF];
__device__ float g_cm1[HF];
__device__ float g_Wm2[HF * HF];
__device__ float g_cm2[HF];
__device__ float g_Wu1[(DF + HF) * HF];
__device__ float g_cu1[HF];
__device__ float g_Wu2[HF * HF];
__device__ float g_cu2[HF];
__device__ float g_agg[(size_t)NODES * HF];
__device__ float g_cnt[NODES];

// ---------------- helpers ----------------
__device__ __forceinline__ float gelu_f(float v) {
    return 0.5f * v * (1.0f + erff(v * 0.70710678118654752440f));
}

__device__ __forceinline__ ull pack2(float v) {
    ull r;
    asm("mov.b64 %0, {%1, %1};" : "=l"(r) : "f"(v));
    return r;
}
__device__ __forceinline__ ull fma2(ull a, ull b, ull c) {
    ull d;
    asm("fma.rn.f32x2 %0, %1, %2, %3;" : "=l"(d) : "l"(a), "l"(b), "l"(c));
    return d;
}
__device__ __forceinline__ float2 unpack2(ull v) {
    float2 f;
    asm("mov.b64 {%0, %1}, %2;" : "=f"(f.x), "=f"(f.y) : "l"(v));
    return f;
}
__device__ __forceinline__ void red_add_v4(float* p, float a, float b, float c, float d) {
    asm volatile("red.global.add.v4.f32 [%0], {%1, %2, %3, %4};"
                 :: "l"(p), "f"(a), "f"(b), "f"(c), "f"(d) : "memory");
}

// ---------------- fold kernel: BN -> weights ----------------
__global__ void fold_kernel(
    const float* __restrict__ m_g1, const float* __restrict__ m_b1,
    const float* __restrict__ m_mu1, const float* __restrict__ m_v1,
    const float* __restrict__ m_W1, const float* __restrict__ m_c1,
    const float* __restrict__ m_g2, const float* __restrict__ m_b2,
    const float* __restrict__ m_mu2, const float* __restrict__ m_v2,
    const float* __restrict__ m_W2, const float* __restrict__ m_c2,
    const float* __restrict__ u_g1, const float* __restrict__ u_b1,
    const float* __restrict__ u_mu1, const float* __restrict__ u_v1,
    const float* __restrict__ u_W1, const float* __restrict__ u_c1,
    const float* __restrict__ u_g2, const float* __restrict__ u_b2,
    const float* __restrict__ u_mu2, const float* __restrict__ u_v2,
    const float* __restrict__ u_W2, const float* __restrict__ u_c2)
{
    int t = blockIdx.x * blockDim.x + threadIdx.x;
    if (t < 4096) {
        int k = t >> 6;
        float s = m_g1[k] * rsqrtf(m_v1[k] + BN_EPS);
        g_Wm1[t] = s * m_W1[t];
    } else if (t < 8192) {
        int i = t - 4096; int k = i >> 6;
        float s = m_g2[k] * rsqrtf(m_v2[k] + BN_EPS);
        g_Wm2[i] = s * m_W2[i];
    } else if (t < 16384) {
        int i = t - 8192; int k = i >> 6;
        float s = u_g1[k] * rsqrtf(u_v1[k] + BN_EPS);
        g_Wu1[i] = s * u_W1[i];
    } else if (t < 20480) {
        int i = t - 16384; int k = i >> 6;
        float s = u_g2[k] * rsqrtf(u_v2[k] + BN_EPS);
        g_Wu2[i] = s * u_W2[i];
    } else if (t < 20544) {
        int j = t - 20480;
        float sum = m_c1[j];
        for (int k = 0; k < DF; k++) {
            float s = m_g1[k] * rsqrtf(m_v1[k] + BN_EPS);
            sum += (m_b1[k] - m_mu1[k] * s) * m_W1[k * HF + j];
        }
        g_cm1[j] = sum;
    } else if (t < 20608) {
        int j = t - 20544;
        float sum = m_c2[j];
        for (int k = 0; k < HF; k++) {
            float s = m_g2[k] * rsqrtf(m_v2[k] + BN_EPS);
            sum += (m_b2[k] - m_mu2[k] * s) * m_W2[k * HF + j];
        }
        g_cm2[j] = sum;
    } else if (t < 20672) {
        int j = t - 20608;
        float sum = u_c1[j];
        for (int k = 0; k < DF + HF; k++) {
            float s = u_g1[k] * rsqrtf(u_v1[k] + BN_EPS);
            sum += (u_b1[k] - u_mu1[k] * s) * u_W1[k * HF + j];
        }
        g_cu1[j] = sum;
    } else if (t < 20736) {
        int j = t - 20672;
        float sum = u_c2[j];
        for (int k = 0; k < HF; k++) {
            float s = u_g2[k] * rsqrtf(u_v2[k] + BN_EPS);
            sum += (u_b2[k] - u_mu2[k] * s) * u_W2[k * HF + j];
        }
        g_cu2[j] = sum;
    }
}

// ---------------- zero accumulators ----------------
__global__ void zero_kernel() {
    size_t total = (size_t)NODES * HF;
    for (size_t i = blockIdx.x * (size_t)blockDim.x + threadIdx.x;
         i < total; i += (size_t)gridDim.x * blockDim.x) {
        g_agg[i] = 0.0f;
        if (i < NODES) g_cnt[i] = 0.0f;
    }
}

// =====================================================================
// FMA2 layer building blocks (64 -> 64), fully unrolled, outputs in regs
// Bias pointer is ALWAYS shared memory -> plain loads only.
// MODE 0: weights from shared memory (LDS.128 as ulonglong2)
// MODE 1: weights from GLOBAL memory via uniform __ldg (L1-broadcast)
// =====================================================================
template <int MODE>
__device__ __forceinline__ void layer64_reg(const float* __restrict__ W,
                                            const float* __restrict__ b,
                                            const float* __restrict__ x,
                                            float* __restrict__ y)
{
#pragma unroll
    for (int q = 0; q < 4; q++) {
        ull acc[8];
        const ulonglong2* bp = (const ulonglong2*)(b + q * 16);
#pragma unroll
        for (int i = 0; i < 4; i++) {
            ulonglong2 bb = bp[i];   // smem bias: plain load
            acc[2 * i] = bb.x; acc[2 * i + 1] = bb.y;
        }
#pragma unroll
        for (int k = 0; k < 64; k++) {
            ull xx = pack2(x[k]);
            const ulonglong2* wp = (const ulonglong2*)(W + k * 64 + q * 16);
#pragma unroll
            for (int i = 0; i < 4; i++) {
                ulonglong2 w = (MODE == 0) ? wp[i] : __ldg(&wp[i]);
                acc[2 * i]     = fma2(xx, w.x, acc[2 * i]);
                acc[2 * i + 1] = fma2(xx, w.y, acc[2 * i + 1]);
            }
        }
#pragma unroll
        for (int i = 0; i < 8; i++) {
            float2 f = unpack2(acc[i]);
            y[q * 16 + 2 * i]     = gelu_f(f.x);
            y[q * 16 + 2 * i + 1] = gelu_f(f.y);
        }
    }
}

// 64 -> 64, smem weights, output gelu written to per-thread smem column (stride 128)
__device__ __forceinline__ void layer64_store(const float* __restrict__ W,
                                              const float* __restrict__ b,
                                              const float* __restrict__ x,
                                              float* __restrict__ col)
{
#pragma unroll
    for (int q = 0; q < 4; q++) {
        ull acc[8];
        const ulonglong2* bp = (const ulonglong2*)(b + q * 16);
#pragma unroll
        for (int i = 0; i < 4; i++) {
            ulonglong2 bb = bp[i];
            acc[2 * i] = bb.x; acc[2 * i + 1] = bb.y;
        }
#pragma unroll
        for (int k = 0; k < 64; k++) {
            ull xx = pack2(x[k]);
            const ulonglong2* wp = (const ulonglong2*)(W + k * 64 + q * 16);
#pragma unroll
            for (int i = 0; i < 4; i++) {
                ulonglong2 w = wp[i];
                acc[2 * i]     = fma2(xx, w.x, acc[2 * i]);
                acc[2 * i + 1] = fma2(xx, w.y, acc[2 * i + 1]);
            }
        }
#pragma unroll
        for (int i = 0; i < 8; i++) {
            float2 f = unpack2(acc[i]);
            col[(q * 16 + 2 * i) * 128]     = gelu_f(f.x);
            col[(q * 16 + 2 * i + 1) * 128] = gelu_f(f.y);
        }
    }
}

// final 64 -> 64 (GLOBAL weights via __ldg), gate with msg column, scatter red.add
__device__ __forceinline__ void layer64_gate(const float* __restrict__ W,
                                             const float* __restrict__ b,
                                             const float* __restrict__ x,
                                             const float* __restrict__ msgcol,
                                             float* __restrict__ aggrow)
{
#pragma unroll
    for (int q = 0; q < 4; q++) {
        ull acc[8];
        const ulonglong2* bp = (const ulonglong2*)(b + q * 16);
#pragma unroll
        for (int i = 0; i < 4; i++) {
            ulonglong2 bb = bp[i];   // smem bias: plain load
            acc[2 * i] = bb.x; acc[2 * i + 1] = bb.y;
        }
#pragma unroll
        for (int k = 0; k < 64; k++) {
            ull xx = pack2(x[k]);
            const ulonglong2* wp = (const ulonglong2*)(W + k * 64 + q * 16);
#pragma unroll
            for (int i = 0; i < 4; i++) {
                ulonglong2 w = __ldg(&wp[i]);
                acc[2 * i]     = fma2(xx, w.x, acc[2 * i]);
                acc[2 * i + 1] = fma2(xx, w.y, acc[2 * i + 1]);
            }
        }
        float e[16];
#pragma unroll
        for (int i = 0; i < 8; i++) {
            float2 f = unpack2(acc[i]);
            e[2 * i]     = gelu_f(f.x);
            e[2 * i + 1] = gelu_f(f.y);
        }
#pragma unroll
        for (int i = 0; i < 4; i++) {
            int j = q * 16 + i * 4;
            float m0 = msgcol[(j + 0) * 128];
            float m1 = msgcol[(j + 1) * 128];
            float m2 = msgcol[(j + 2) * 128];
            float m3 = msgcol[(j + 3) * 128];
            red_add_v4(aggrow + j, m0 * e[i * 4 + 0], m1 * e[i * 4 + 1],
                                   m2 * e[i * 4 + 2], m3 * e[i * 4 + 3]);
        }
    }
}

// ---------------- edge kernel ----------------
// dynamic smem (floats): Wm1 4096 | Wm2 4096 | sb 256 | msg 8192  = 16640 (~65KB)
__global__ void __launch_bounds__(128, 3)
edge_kernel(const float* __restrict__ nf, const float* __restrict__ ef,
            const int* __restrict__ src, const int* __restrict__ dst,
            const float* __restrict__ We1, const float* __restrict__ ce1,
            const float* __restrict__ We2, const float* __restrict__ ce2,
            int E)
{
    extern __shared__ float sm[];
    float* sWm1 = sm;
    float* sWm2 = sm + 4096;
    float* sb   = sm + 8192;   // [0:64) cm1, [64:128) cm2, [128:192) ce1, [192:256) ce2
    float* msg  = sm + 8448;

    for (int i = threadIdx.x; i < 4096; i += 128) {
        sWm1[i] = g_Wm1[i];
        sWm2[i] = g_Wm2[i];
    }
    if (threadIdx.x < 64) {
        int i = threadIdx.x;
        sb[i]       = g_cm1[i];
        sb[64 + i]  = g_cm2[i];
        sb[128 + i] = ce1[i];
        sb[192 + i] = ce2[i];
    }
    __syncthreads();

    float* msgcol = msg + threadIdx.x;

    for (int e = blockIdx.x * 128 + threadIdx.x; e < E; e += gridDim.x * 128) {
        int d = dst[e];
        int s = src[e];
        float x[64], y[64];

        // gather neighbour features (L2-resident)
        const float4* nrow = (const float4*)(nf + (size_t)d * 64);
#pragma unroll
        for (int k = 0; k < 16; k++) {
            float4 v = __ldg(nrow + k);
            x[4 * k + 0] = v.x; x[4 * k + 1] = v.y;
            x[4 * k + 2] = v.z; x[4 * k + 3] = v.w;
        }
        // message MLP (BN folded into weights)
        layer64_reg<0>(sWm1, sb, x, y);
        layer64_store(sWm2, sb + 64, y, msgcol);

        // edge transformer
        const float4* erow = (const float4*)(ef + (size_t)e * 64);
#pragma unroll
        for (int k = 0; k < 16; k++) {
            float4 v = __ldg(erow + k);
            x[4 * k + 0] = v.x; x[4 * k + 1] = v.y;
            x[4 * k + 2] = v.z; x[4 * k + 3] = v.w;
        }
        layer64_reg<1>(We1, sb + 128, x, y);
        layer64_gate(We2, sb + 192, y, msgcol, g_agg + (size_t)s * 64);
        atomicAdd(&g_cnt[s], 1.0f);
    }
}

// ---------------- node kernel: mean + update MLP (FMA2 inner loops) ----------------
// smem (floats): Wu1 8192 | Wu2 4096 | biases 128 | io 8192 = 20608 (~80.5KB)
__global__ void __launch_bounds__(128, 2)
node_kernel(const float* __restrict__ nf, float* __restrict__ out, int N)
{
    extern __shared__ float sm[];
    float* sW1 = sm;
    float* sW2 = sm + 8192;
    float* sb  = sm + 12288;  // [0:64) cu1, [64:128) cu2
    float* io  = sm + 12416;

    for (int i = threadIdx.x; i < 8192; i += 128) sW1[i] = g_Wu1[i];
    for (int i = threadIdx.x; i < 4096; i += 128) sW2[i] = g_Wu2[i];
    if (threadIdx.x < 64) {
        sb[threadIdx.x]      = g_cu1[threadIdx.x];
        sb[64 + threadIdx.x] = g_cu2[threadIdx.x];
    }
    __syncthreads();

    int n = blockIdx.x * 128 + threadIdx.x;
    if (n >= N) return;

    float x[128];
    const float4* nrow = (const float4*)(nf + (size_t)n * 64);
#pragma unroll
    for (int k = 0; k < 16; k++) {
        float4 v = __ldg(nrow + k);
        x[4 * k + 0] = v.x; x[4 * k + 1] = v.y;
        x[4 * k + 2] = v.z; x[4 * k + 3] = v.w;
    }
    float c = g_cnt[n];
    float inv = 1.0f / fmaxf(c, 1.0f);
    const float4* arow = (const float4*)(g_agg + (size_t)n * 64);
#pragma unroll
    for (int k = 0; k < 16; k++) {
        float4 v = arow[k];
        x[64 + 4 * k + 0] = v.x * inv; x[64 + 4 * k + 1] = v.y * inv;
        x[64 + 4 * k + 2] = v.z * inv; x[64 + 4 * k + 3] = v.w * inv;
    }

    float* col = io + threadIdx.x;
    // layer 1: 128 -> 64
#pragma unroll 1
    for (int q = 0; q < 16; q++) {
        const ulonglong2* bp = (const ulonglong2*)(sb + q * 4);
        ulonglong2 bb = bp[0];
        ull a0 = bb.x, a1 = bb.y;
        const float* wp = sW1 + q * 4;
#pragma unroll
        for (int k = 0; k < 128; k++) {
            ull xx = pack2(x[k]);
            ulonglong2 w = *(const ulonglong2*)(wp + k * 64);
            a0 = fma2(xx, w.x, a0);
            a1 = fma2(xx, w.y, a1);
        }
        float2 f0 = unpack2(a0), f1 = unpack2(a1);
        col[(q * 4 + 0) * 128] = gelu_f(f0.x);
        col[(q * 4 + 1) * 128] = gelu_f(f0.y);
        col[(q * 4 + 2) * 128] = gelu_f(f1.x);
        col[(q * 4 + 3) * 128] = gelu_f(f1.y);
    }
#pragma unroll
    for (int k = 0; k < 64; k++) x[k] = col[k * 128];
    // layer 2: 64 -> 64, write output directly
    float4* orow = (float4*)(out + (size_t)n * 64);
#pragma unroll 1
    for (int q = 0; q < 16; q++) {
        const ulonglong2* bp = (const ulonglong2*)(sb + 64 + q * 4);
        ulonglong2 bb = bp[0];
        ull a0 = bb.x, a1 = bb.y;
        const float* wp = sW2 + q * 4;
#pragma unroll
        for (int k = 0; k < 64; k++) {
            ull xx = pack2(x[k]);
            ulonglong2 w = *(const ulonglong2*)(wp + k * 64);
            a0 = fma2(xx, w.x, a0);
            a1 = fma2(xx, w.y, a1);
        }
        float2 f0 = unpack2(a0), f1 = unpack2(a1);
        float4 o;
        o.x = gelu_f(f0.x); o.y = gelu_f(f0.y);
        o.z = gelu_f(f1.x); o.w = gelu_f(f1.y);
        orow[q] = o;
    }
}

// ---------------- launch ----------------
extern "C" void kernel_launch(void* const* d_in, const int* in_sizes, int n_in,
                              void* d_out, int out_size)
{
    bool dictOrder = (in_sizes[2] > 64);
    const float* nf = (const float*)d_in[0];
    const float* ef = (const float*)d_in[1];
    const int* src = (const int*)d_in[dictOrder ? 2 : 30];
    const int* dst = (const int*)d_in[dictOrder ? 3 : 31];
    int p0 = dictOrder ? 4 : 2;
    const float* P[28];
    for (int i = 0; i < 28; i++) P[i] = (const float*)d_in[p0 + i];

    int E = in_sizes[1] / 64;
    int N = in_sizes[0] / 64;

    cudaFuncSetAttribute(edge_kernel, cudaFuncAttributeMaxDynamicSharedMemorySize,
                         16640 * (int)sizeof(float));
    cudaFuncSetAttribute(node_kernel, cudaFuncAttributeMaxDynamicSharedMemorySize,
                         20608 * (int)sizeof(float));

    fold_kernel<<<(20736 + 255) / 256, 256>>>(
        P[0], P[1], P[2], P[3], P[4], P[5], P[6], P[7], P[8], P[9], P[10], P[11],
        P[16], P[17], P[18], P[19], P[20], P[21], P[22], P[23], P[24], P[25], P[26], P[27]);
    zero_kernel<<<2048, 256>>>();
    edge_kernel<<<444, 128, 16640 * sizeof(float)>>>(
        nf, ef, src, dst, P[12], P[13], P[14], P[15], E);
    node_kernel<<<(N + 127) / 128, 128, 20608 * sizeof(float)>>>(
        nf, (float*)d_out, N);
}

// round 5
// speedup vs baseline: 1.1462x; 1.1462x over previous
#include <cuda_runtime.h>
#include <cuda_bf16.h>
#include <math.h>

#define NODES 50000
#define DF 64
#define HF 64
#define BN_EPS 1e-3f

typedef unsigned long long ull;

// ---------------- device scratch (static, no allocs) ----------------
__device__ float g_Wm1[DF * HF];
__device__ float g_cm1[HF];
__device__ float g_Wm2[HF * HF];
__device__ float g_cm2[HF];
__device__ float g_Wu1[(DF + HF) * HF];
__device__ float g_cu1[HF];
__device__ float g_Wu2[HF * HF];
__device__ float g_cu2[HF];
__device__ float g_agg[(size_t)NODES * HF];
__device__ float g_cnt[NODES];

// ---------------- helpers ----------------
__device__ __forceinline__ float gelu_f(float v) {
    return 0.5f * v * (1.0f + erff(v * 0.70710678118654752440f));
}
__device__ __forceinline__ ull pack2(float v) {
    ull r;
    asm("mov.b64 %0, {%1, %1};" : "=l"(r) : "f"(v));
    return r;
}
__device__ __forceinline__ ull fma2(ull a, ull b, ull c) {
    ull d;
    asm("fma.rn.f32x2 %0, %1, %2, %3;" : "=l"(d) : "l"(a), "l"(b), "l"(c));
    return d;
}
__device__ __forceinline__ float2 unpack2(ull v) {
    float2 f;
    asm("mov.b64 {%0, %1}, %2;" : "=f"(f.x), "=f"(f.y) : "l"(v));
    return f;
}
__device__ __forceinline__ void red_add_v4(float* p, float a, float b, float c, float d) {
    asm volatile("red.global.add.v4.f32 [%0], {%1, %2, %3, %4};"
                 :: "l"(p), "f"(a), "f"(b), "f"(c), "f"(d) : "memory");
}
__device__ __forceinline__ void cp_async16(unsigned saddr, const void* gptr) {
    asm volatile("cp.async.cg.shared.global [%0], [%1], 16;" :: "r"(saddr), "l"(gptr));
}

// ---------------- fold kernel: BN -> weights ----------------
__global__ void fold_kernel(
    const float* __restrict__ m_g1, const float* __restrict__ m_b1,
    const float* __restrict__ m_mu1, const float* __restrict__ m_v1,
    const float* __restrict__ m_W1, const float* __restrict__ m_c1,
    const float* __restrict__ m_g2, const float* __restrict__ m_b2,
    const float* __restrict__ m_mu2, const float* __restrict__ m_v2,
    const float* __restrict__ m_W2, const float* __restrict__ m_c2,
    const float* __restrict__ u_g1, const float* __restrict__ u_b1,
    const float* __restrict__ u_mu1, const float* __restrict__ u_v1,
    const float* __restrict__ u_W1, const float* __restrict__ u_c1,
    const float* __restrict__ u_g2, const float* __restrict__ u_b2,
    const float* __restrict__ u_mu2, const float* __restrict__ u_v2,
    const float* __restrict__ u_W2, const float* __restrict__ u_c2)
{
    int t = blockIdx.x * blockDim.x + threadIdx.x;
    if (t < 4096) {
        int k = t >> 6;
        float s = m_g1[k] * rsqrtf(m_v1[k] + BN_EPS);
        g_Wm1[t] = s * m_W1[t];
    } else if (t < 8192) {
        int i = t - 4096; int k = i >> 6;
        float s = m_g2[k] * rsqrtf(m_v2[k] + BN_EPS);
        g_Wm2[i] = s * m_W2[i];
    } else if (t < 16384) {
        int i = t - 8192; int k = i >> 6;
        float s = u_g1[k] * rsqrtf(u_v1[k] + BN_EPS);
        g_Wu1[i] = s * u_W1[i];
    } else if (t < 20480) {
        int i = t - 16384; int k = i >> 6;
        float s = u_g2[k] * rsqrtf(u_v2[k] + BN_EPS);
        g_Wu2[i] = s * u_W2[i];
    } else if (t < 20544) {
        int j = t - 20480;
        float sum = m_c1[j];
        for (int k = 0; k < DF; k++) {
            float s = m_g1[k] * rsqrtf(m_v1[k] + BN_EPS);
            sum += (m_b1[k] - m_mu1[k] * s) * m_W1[k * HF + j];
        }
        g_cm1[j] = sum;
    } else if (t < 20608) {
        int j = t - 20544;
        float sum = m_c2[j];
        for (int k = 0; k < HF; k++) {
            float s = m_g2[k] * rsqrtf(m_v2[k] + BN_EPS);
            sum += (m_b2[k] - m_mu2[k] * s) * m_W2[k * HF + j];
        }
        g_cm2[j] = sum;
    } else if (t < 20672) {
        int j = t - 20608;
        float sum = u_c1[j];
        for (int k = 0; k < DF + HF; k++) {
            float s = u_g1[k] * rsqrtf(u_v1[k] + BN_EPS);
            sum += (u_b1[k] - u_mu1[k] * s) * u_W1[k * HF + j];
        }
        g_cu1[j] = sum;
    } else if (t < 20736) {
        int j = t - 20672;
        float sum = u_c2[j];
        for (int k = 0; k < HF; k++) {
            float s = u_g2[k] * rsqrtf(u_v2[k] + BN_EPS);
            sum += (u_b2[k] - u_mu2[k] * s) * u_W2[k * HF + j];
        }
        g_cu2[j] = sum;
    }
}

// ---------------- zero accumulators ----------------
__global__ void zero_kernel() {
    size_t total = (size_t)NODES * HF;
    for (size_t i = blockIdx.x * (size_t)blockDim.x + threadIdx.x;
         i < total; i += (size_t)gridDim.x * blockDim.x) {
        g_agg[i] = 0.0f;
        if (i < NODES) g_cnt[i] = 0.0f;
    }
}

// =====================================================================
// Register-tiled GEMM over a 128-edge x 64-feature tile.
// 256 threads: og = t&7 (8 output-groups x 8 outputs), eg = t>>3 (32 edge-
// groups x 4 edges). Per thread: 4x8 output tile in 16 f32x2 accumulators.
// sIn/sOut rows padded to 68 floats (bank-conflict-free 4-edge x loads).
// =====================================================================
#define ROWP 68

__device__ __forceinline__ void gemm_acc(const float* __restrict__ sIn,
                                         const float* __restrict__ sW,
                                         const float* __restrict__ sbias,
                                         int t, ull acc[4][4])
{
    int og = t & 7, eg = t >> 3;
    const float* xin = sIn + eg * 4 * ROWP;
    {
        const ulonglong2* bp = (const ulonglong2*)(sbias + og * 8);
        ulonglong2 b0 = bp[0], b1 = bp[1];
#pragma unroll
        for (int e = 0; e < 4; e++) {
            acc[e][0] = b0.x; acc[e][1] = b0.y;
            acc[e][2] = b1.x; acc[e][3] = b1.y;
        }
    }
#pragma unroll
    for (int kc = 0; kc < 16; kc++) {
        float4 xv[4];
#pragma unroll
        for (int e = 0; e < 4; e++)
            xv[e] = *(const float4*)(xin + e * ROWP + kc * 4);
#pragma unroll
        for (int kk = 0; kk < 4; kk++) {
            const ulonglong2* wp =
                (const ulonglong2*)(sW + (kc * 4 + kk) * 64 + og * 8);
            ulonglong2 wa = wp[0], wb = wp[1];
#pragma unroll
            for (int e = 0; e < 4; e++) {
                float xs = (kk == 0) ? xv[e].x : (kk == 1) ? xv[e].y
                         : (kk == 2) ? xv[e].z : xv[e].w;
                ull xx = pack2(xs);
                acc[e][0] = fma2(xx, wa.x, acc[e][0]);
                acc[e][1] = fma2(xx, wa.y, acc[e][1]);
                acc[e][2] = fma2(xx, wb.x, acc[e][2]);
                acc[e][3] = fma2(xx, wb.y, acc[e][3]);
            }
        }
    }
}

__device__ __forceinline__ void gemm_tile(const float* __restrict__ sIn,
                                          const float* __restrict__ sW,
                                          const float* __restrict__ sbias,
                                          float* __restrict__ sOut, int t)
{
    ull acc[4][4];
    gemm_acc(sIn, sW, sbias, t, acc);
    int og = t & 7, eg = t >> 3;
#pragma unroll
    for (int e = 0; e < 4; e++) {
        float2 f0 = unpack2(acc[e][0]), f1 = unpack2(acc[e][1]);
        float2 f2 = unpack2(acc[e][2]), f3 = unpack2(acc[e][3]);
        float4 o0, o1;
        o0.x = gelu_f(f0.x); o0.y = gelu_f(f0.y);
        o0.z = gelu_f(f1.x); o0.w = gelu_f(f1.y);
        o1.x = gelu_f(f2.x); o1.y = gelu_f(f2.y);
        o1.z = gelu_f(f3.x); o1.w = gelu_f(f3.y);
        float* op = sOut + (eg * 4 + e) * ROWP + og * 8;
        *(float4*)op = o0;
        *(float4*)(op + 4) = o1;
    }
}

__device__ __forceinline__ void gemm_gate(const float* __restrict__ sIn,
                                          const float* __restrict__ sW,
                                          const float* __restrict__ sbias,
                                          const float* __restrict__ sMsg,
                                          const int* __restrict__ sSrc,
                                          int nvalid, int t)
{
    ull acc[4][4];
    gemm_acc(sIn, sW, sbias, t, acc);
    int og = t & 7, eg = t >> 3;
#pragma unroll
    for (int e = 0; e < 4; e++) {
        int ei = eg * 4 + e;
        if (ei < nvalid) {
            float2 f0 = unpack2(acc[e][0]), f1 = unpack2(acc[e][1]);
            float2 f2 = unpack2(acc[e][2]), f3 = unpack2(acc[e][3]);
            float g0 = gelu_f(f0.x), g1 = gelu_f(f0.y);
            float g2 = gelu_f(f1.x), g3 = gelu_f(f1.y);
            float g4 = gelu_f(f2.x), g5 = gelu_f(f2.y);
            float g6 = gelu_f(f3.x), g7 = gelu_f(f3.y);
            const float* mp = sMsg + ei * ROWP + og * 8;
            float4 m0 = *(const float4*)mp;
            float4 m1 = *(const float4*)(mp + 4);
            float* ap = g_agg + (size_t)sSrc[ei] * 64 + og * 8;
            red_add_v4(ap,     m0.x * g0, m0.y * g1, m0.z * g2, m0.w * g3);
            red_add_v4(ap + 4, m1.x * g4, m1.y * g5, m1.z * g6, m1.w * g7);
        }
    }
}

// ---------------- edge kernel: tiled fused message+gate+scatter ----------------
// smem floats: Wm1 4096 | Wm2 4096 | We1 4096 | We2 4096 | bias 256 | src 128
//              | A 8704 | B 8704 | C 8704  -> 42880 floats (~168KB)
#define SM_B   16384
#define SM_SRC 16640
#define SM_A   16768
#define SM_SB  (16768 + 8704)
#define SM_SC  (16768 + 2 * 8704)
#define SM_TOT (16768 + 3 * 8704)

__global__ void __launch_bounds__(256, 1)
edge_kernel(const float* __restrict__ nf, const float* __restrict__ ef,
            const int* __restrict__ src, const int* __restrict__ dst,
            const float* __restrict__ We1, const float* __restrict__ ce1,
            const float* __restrict__ We2, const float* __restrict__ ce2,
            int E)
{
    extern __shared__ float sm[];
    float* sWm1 = sm;
    float* sWm2 = sm + 4096;
    float* sWe1 = sm + 8192;
    float* sWe2 = sm + 12288;
    float* sb   = sm + SM_B;
    int*   sSrc = (int*)(sm + SM_SRC);
    float* sA   = sm + SM_A;
    float* sB   = sm + SM_SB;
    float* sC   = sm + SM_SC;

    int t = threadIdx.x;
    int e0 = blockIdx.x * 128;
    int nvalid = min(128, E - e0);
    unsigned sbase = (unsigned)__cvta_generic_to_shared(sm);

    // group 0: gather nbr features -> sA
    for (int i = t; i < 2048; i += 256) {
        int e = i >> 4, q = i & 15;
        int ee = (e < nvalid) ? e : 0;
        int d = __ldg(dst + e0 + ee);
        cp_async16(sbase + (SM_A + e * ROWP + q * 4) * 4,
                   nf + (size_t)d * 64 + q * 4);
    }
    asm volatile("cp.async.commit_group;" ::: "memory");
    // group 1: stream edge features -> sC
    for (int i = t; i < 2048; i += 256) {
        int e = i >> 4, q = i & 15;
        int ee = (e < nvalid) ? e : 0;
        cp_async16(sbase + (SM_SC + e * ROWP + q * 4) * 4,
                   ef + (size_t)(e0 + ee) * 64 + q * 4);
    }
    asm volatile("cp.async.commit_group;" ::: "memory");

    // weights + biases + src (plain loads, overlap with cp.async)
    for (int i = t; i < 1024; i += 256) {
        ((float4*)sWm1)[i] = ((const float4*)g_Wm1)[i];
        ((float4*)sWm2)[i] = ((const float4*)g_Wm2)[i];
        ((float4*)sWe1)[i] = __ldg((const float4*)We1 + i);
        ((float4*)sWe2)[i] = __ldg((const float4*)We2 + i);
    }
    if (t < 64) {
        sb[t]        = g_cm1[t];
        sb[64 + t]   = g_cm2[t];
        sb[128 + t]  = __ldg(ce1 + t);
        sb[192 + t]  = __ldg(ce2 + t);
    }
    if (t < 128) sSrc[t] = (t < nvalid) ? src[e0 + t] : 0;

    asm volatile("cp.async.wait_group 1;" ::: "memory");
    __syncthreads();
    gemm_tile(sA, sWm1, sb, sB, t);          // nbr -> h
    __syncthreads();
    gemm_tile(sB, sWm2, sb + 64, sA, t);     // h -> msg (sA)
    asm volatile("cp.async.wait_group 0;" ::: "memory");
    __syncthreads();
    gemm_tile(sC, sWe1, sb + 128, sB, t);    // ef -> er1 (sB)
    __syncthreads();
    gemm_gate(sB, sWe2, sb + 192, sA, sSrc, nvalid, t);  // er2*msg -> scatter

    if ((t & 7) == 0) {
        int eg = t >> 3;
#pragma unroll
        for (int e = 0; e < 4; e++) {
            int ei = eg * 4 + e;
            if (ei < nvalid) atomicAdd(&g_cnt[sSrc[ei]], 1.0f);
        }
    }
}

// ---------------- node kernel: mean + update MLP ----------------
// smem (floats): Wu1 8192 | Wu2 4096 | biases 128 | io 8192 = 20608 (~80.5KB)
__global__ void __launch_bounds__(128, 2)
node_kernel(const float* __restrict__ nf, float* __restrict__ out, int N)
{
    extern __shared__ float sm[];
    float* sW1 = sm;
    float* sW2 = sm + 8192;
    float* sb  = sm + 12288;
    float* io  = sm + 12416;

    for (int i = threadIdx.x; i < 8192; i += 128) sW1[i] = g_Wu1[i];
    for (int i = threadIdx.x; i < 4096; i += 128) sW2[i] = g_Wu2[i];
    if (threadIdx.x < 64) {
        sb[threadIdx.x]      = g_cu1[threadIdx.x];
        sb[64 + threadIdx.x] = g_cu2[threadIdx.x];
    }
    __syncthreads();

    int n = blockIdx.x * 128 + threadIdx.x;
    if (n >= N) return;

    float x[128];
    const float4* nrow = (const float4*)(nf + (size_t)n * 64);
#pragma unroll
    for (int k = 0; k < 16; k++) {
        float4 v = __ldg(nrow + k);
        x[4 * k + 0] = v.x; x[4 * k + 1] = v.y;
        x[4 * k + 2] = v.z; x[4 * k + 3] = v.w;
    }
    float c = g_cnt[n];
    float inv = 1.0f / fmaxf(c, 1.0f);
    const float4* arow = (const float4*)(g_agg + (size_t)n * 64);
#pragma unroll
    for (int k = 0; k < 16; k++) {
        float4 v = arow[k];
        x[64 + 4 * k + 0] = v.x * inv; x[64 + 4 * k + 1] = v.y * inv;
        x[64 + 4 * k + 2] = v.z * inv; x[64 + 4 * k + 3] = v.w * inv;
    }

    float* col = io + threadIdx.x;
#pragma unroll 1
    for (int q = 0; q < 16; q++) {
        const ulonglong2* bp = (const ulonglong2*)(sb + q * 4);
        ulonglong2 bb = bp[0];
        ull a0 = bb.x, a1 = bb.y;
        const float* wp = sW1 + q * 4;
#pragma unroll
        for (int k = 0; k < 128; k++) {
            ull xx = pack2(x[k]);
            ulonglong2 w = *(const ulonglong2*)(wp + k * 64);
            a0 = fma2(xx, w.x, a0);
            a1 = fma2(xx, w.y, a1);
        }
        float2 f0 = unpack2(a0), f1 = unpack2(a1);
        col[(q * 4 + 0) * 128] = gelu_f(f0.x);
        col[(q * 4 + 1) * 128] = gelu_f(f0.y);
        col[(q * 4 + 2) * 128] = gelu_f(f1.x);
        col[(q * 4 + 3) * 128] = gelu_f(f1.y);
    }
#pragma unroll
    for (int k = 0; k < 64; k++) x[k] = col[k * 128];
    float4* orow = (float4*)(out + (size_t)n * 64);
#pragma unroll 1
    for (int q = 0; q < 16; q++) {
        const ulonglong2* bp = (const ulonglong2*)(sb + 64 + q * 4);
        ulonglong2 bb = bp[0];
        ull a0 = bb.x, a1 = bb.y;
        const float* wp = sW2 + q * 4;
#pragma unroll
        for (int k = 0; k < 64; k++) {
            ull xx = pack2(x[k]);
            ulonglong2 w = *(const ulonglong2*)(wp + k * 64);
            a0 = fma2(xx, w.x, a0);
            a1 = fma2(xx, w.y, a1);
        }
        float2 f0 = unpack2(a0), f1 = unpack2(a1);
        float4 o;
        o.x = gelu_f(f0.x); o.y = gelu_f(f0.y);
        o.z = gelu_f(f1.x); o.w = gelu_f(f1.y);
        orow[q] = o;
    }
}

// ---------------- launch ----------------
extern "C" void kernel_launch(void* const* d_in, const int* in_sizes, int n_in,
                              void* d_out, int out_size)
{
    bool dictOrder = (in_sizes[2] > 64);
    const float* nf = (const float*)d_in[0];
    const float* ef = (const float*)d_in[1];
    const int* src = (const int*)d_in[dictOrder ? 2 : 30];
    const int* dst = (const int*)d_in[dictOrder ? 3 : 31];
    int p0 = dictOrder ? 4 : 2;
    const float* P[28];
    for (int i = 0; i < 28; i++) P[i] = (const float*)d_in[p0 + i];

    int E = in_sizes[1] / 64;
    int N = in_sizes[0] / 64;

    cudaFuncSetAttribute(edge_kernel, cudaFuncAttributeMaxDynamicSharedMemorySize,
                         SM_TOT * (int)sizeof(float));
    cudaFuncSetAttribute(node_kernel, cudaFuncAttributeMaxDynamicSharedMemorySize,
                         20608 * (int)sizeof(float));

    fold_kernel<<<(20736 + 255) / 256, 256>>>(
        P[0], P[1], P[2], P[3], P[4], P[5], P[6], P[7], P[8], P[9], P[10], P[11],
        P[16], P[17], P[18], P[19], P[20], P[21], P[22], P[23], P[24], P[25], P[26], P[27]);
    zero_kernel<<<2048, 256>>>();
    edge_kernel<<<(E + 127) / 128, 256, SM_TOT * sizeof(float)>>>(
        nf, ef, src, dst, P[12], P[13], P[14], P[15], E);
    node_kernel<<<(N + 127) / 128, 128, 20608 * sizeof(float)>>>(
        nf, (float*)d_out, N);
}

// round 6
// speedup vs baseline: 2.4296x; 2.1198x over previous
#include <cuda_runtime.h>
#include <cuda_bf16.h>
#include <math.h>

#define NODES 50000
#define DF 64
#define HF 64
#define BN_EPS 1e-3f

typedef unsigned long long ull;

// ---------------- device scratch (static, no allocs) ----------------
__device__ float g_Wm1[DF * HF];
__device__ float g_cm1[HF];
__device__ float g_Wm2[HF * HF];
__device__ float g_cm2[HF];
__device__ float g_Wu1[(DF + HF) * HF];
__device__ float g_cu1[HF];
__device__ float g_Wu2[HF * HF];
__device__ float g_cu2[HF];
__device__ float g_agg[(size_t)NODES * HF];   // segment sums
__device__ float g_cnt[NODES];                // segment counts
__device__ float g_msg[(size_t)NODES * HF];   // per-node precomputed message

// ---------------- helpers ----------------
__device__ __forceinline__ float gelu_f(float v) {
    return 0.5f * v * (1.0f + erff(v * 0.70710678118654752440f));
}
__device__ __forceinline__ ull pack2(float v) {
    ull r;
    asm("mov.b64 %0, {%1, %1};" : "=l"(r) : "f"(v));
    return r;
}
__device__ __forceinline__ ull fma2(ull a, ull b, ull c) {
    ull d;
    asm("fma.rn.f32x2 %0, %1, %2, %3;" : "=l"(d) : "l"(a), "l"(b), "l"(c));
    return d;
}
__device__ __forceinline__ float2 unpack2(ull v) {
    float2 f;
    asm("mov.b64 {%0, %1}, %2;" : "=f"(f.x), "=f"(f.y) : "l"(v));
    return f;
}
__device__ __forceinline__ void red_add_v4(float* p, float a, float b, float c, float d) {
    asm volatile("red.global.add.v4.f32 [%0], {%1, %2, %3, %4};"
                 :: "l"(p), "f"(a), "f"(b), "f"(c), "f"(d) : "memory");
}
__device__ __forceinline__ void cp_async16(unsigned saddr, const void* gptr) {
    asm volatile("cp.async.cg.shared.global [%0], [%1], 16;" :: "r"(saddr), "l"(gptr));
}

// ---------------- fold kernel: BN -> weights ----------------
__global__ void fold_kernel(
    const float* __restrict__ m_g1, const float* __restrict__ m_b1,
    const float* __restrict__ m_mu1, const float* __restrict__ m_v1,
    const float* __restrict__ m_W1, const float* __restrict__ m_c1,
    const float* __restrict__ m_g2, const float* __restrict__ m_b2,
    const float* __restrict__ m_mu2, const float* __restrict__ m_v2,
    const float* __restrict__ m_W2, const float* __restrict__ m_c2,
    const float* __restrict__ u_g1, const float* __restrict__ u_b1,
    const float* __restrict__ u_mu1, const float* __restrict__ u_v1,
    const float* __restrict__ u_W1, const float* __restrict__ u_c1,
    const float* __restrict__ u_g2, const float* __restrict__ u_b2,
    const float* __restrict__ u_mu2, const float* __restrict__ u_v2,
    const float* __restrict__ u_W2, const float* __restrict__ u_c2)
{
    int t = blockIdx.x * blockDim.x + threadIdx.x;
    if (t < 4096) {
        int k = t >> 6;
        float s = m_g1[k] * rsqrtf(m_v1[k] + BN_EPS);
        g_Wm1[t] = s * m_W1[t];
    } else if (t < 8192) {
        int i = t - 4096; int k = i >> 6;
        float s = m_g2[k] * rsqrtf(m_v2[k] + BN_EPS);
        g_Wm2[i] = s * m_W2[i];
    } else if (t < 16384) {
        int i = t - 8192; int k = i >> 6;
        float s = u_g1[k] * rsqrtf(u_v1[k] + BN_EPS);
        g_Wu1[i] = s * u_W1[i];
    } else if (t < 20480) {
        int i = t - 16384; int k = i >> 6;
        float s = u_g2[k] * rsqrtf(u_v2[k] + BN_EPS);
        g_Wu2[i] = s * u_W2[i];
    } else if (t < 20544) {
        int j = t - 20480;
        float sum = m_c1[j];
        for (int k = 0; k < DF; k++) {
            float s = m_g1[k] * rsqrtf(m_v1[k] + BN_EPS);
            sum += (m_b1[k] - m_mu1[k] * s) * m_W1[k * HF + j];
        }
        g_cm1[j] = sum;
    } else if (t < 20608) {
        int j = t - 20544;
        float sum = m_c2[j];
        for (int k = 0; k < HF; k++) {
            float s = m_g2[k] * rsqrtf(m_v2[k] + BN_EPS);
            sum += (m_b2[k] - m_mu2[k] * s) * m_W2[k * HF + j];
        }
        g_cm2[j] = sum;
    } else if (t < 20672) {
        int j = t - 20608;
        float sum = u_c1[j];
        for (int k = 0; k < DF + HF; k++) {
            float s = u_g1[k] * rsqrtf(u_v1[k] + BN_EPS);
            sum += (u_b1[k] - u_mu1[k] * s) * u_W1[k * HF + j];
        }
        g_cu1[j] = sum;
    } else if (t < 20736) {
        int j = t - 20672;
        float sum = u_c2[j];
        for (int k = 0; k < HF; k++) {
            float s = u_g2[k] * rsqrtf(u_v2[k] + BN_EPS);
            sum += (u_b2[k] - u_mu2[k] * s) * u_W2[k * HF + j];
        }
        g_cu2[j] = sum;
    }
}

// ---------------- zero accumulators ----------------
__global__ void zero_kernel() {
    size_t total = (size_t)NODES * HF;
    for (size_t i = blockIdx.x * (size_t)blockDim.x + threadIdx.x;
         i < total; i += (size_t)gridDim.x * blockDim.x) {
        g_agg[i] = 0.0f;
        if (i < NODES) g_cnt[i] = 0.0f;
    }
}

// =====================================================================
// Register-tiled GEMM over a 128-row x 64-feature tile.
// 256 threads: og = t&7 (8 outputs each), eg = t>>3 (4 rows each).
// Per thread: 4x8 output tile in 16 f32x2 accumulators.
// =====================================================================
#define ROWP 68

__device__ __forceinline__ void gemm_acc(const float* __restrict__ sIn,
                                         const float* __restrict__ sW,
                                         const float* __restrict__ sbias,
                                         int t, ull acc[4][4])
{
    int og = t & 7, eg = t >> 3;
    const float* xin = sIn + eg * 4 * ROWP;
    {
        const ulonglong2* bp = (const ulonglong2*)(sbias + og * 8);
        ulonglong2 b0 = bp[0], b1 = bp[1];
#pragma unroll
        for (int e = 0; e < 4; e++) {
            acc[e][0] = b0.x; acc[e][1] = b0.y;
            acc[e][2] = b1.x; acc[e][3] = b1.y;
        }
    }
#pragma unroll
    for (int kc = 0; kc < 16; kc++) {
        float4 xv[4];
#pragma unroll
        for (int e = 0; e < 4; e++)
            xv[e] = *(const float4*)(xin + e * ROWP + kc * 4);
#pragma unroll
        for (int kk = 0; kk < 4; kk++) {
            const ulonglong2* wp =
                (const ulonglong2*)(sW + (kc * 4 + kk) * 64 + og * 8);
            ulonglong2 wa = wp[0], wb = wp[1];
#pragma unroll
            for (int e = 0; e < 4; e++) {
                float xs = (kk == 0) ? xv[e].x : (kk == 1) ? xv[e].y
                         : (kk == 2) ? xv[e].z : xv[e].w;
                ull xx = pack2(xs);
                acc[e][0] = fma2(xx, wa.x, acc[e][0]);
                acc[e][1] = fma2(xx, wa.y, acc[e][1]);
                acc[e][2] = fma2(xx, wb.x, acc[e][2]);
                acc[e][3] = fma2(xx, wb.y, acc[e][3]);
            }
        }
    }
}

// gelu epilogue -> smem tile
__device__ __forceinline__ void gemm_tile(const float* __restrict__ sIn,
                                          const float* __restrict__ sW,
                                          const float* __restrict__ sbias,
                                          float* __restrict__ sOut, int t)
{
    ull acc[4][4];
    gemm_acc(sIn, sW, sbias, t, acc);
    int og = t & 7, eg = t >> 3;
#pragma unroll
    for (int e = 0; e < 4; e++) {
        float2 f0 = unpack2(acc[e][0]), f1 = unpack2(acc[e][1]);
        float2 f2 = unpack2(acc[e][2]), f3 = unpack2(acc[e][3]);
        float4 o0, o1;
        o0.x = gelu_f(f0.x); o0.y = gelu_f(f0.y);
        o0.z = gelu_f(f1.x); o0.w = gelu_f(f1.y);
        o1.x = gelu_f(f2.x); o1.y = gelu_f(f2.y);
        o1.z = gelu_f(f3.x); o1.w = gelu_f(f3.y);
        float* op = sOut + (eg * 4 + e) * ROWP + og * 8;
        *(float4*)op = o0;
        *(float4*)(op + 4) = o1;
    }
}

// gelu epilogue -> global g_msg rows (msg precompute)
__device__ __forceinline__ void gemm_out(const float* __restrict__ sIn,
                                         const float* __restrict__ sW,
                                         const float* __restrict__ sbias,
                                         int n0, int nvalid, int t)
{
    ull acc[4][4];
    gemm_acc(sIn, sW, sbias, t, acc);
    int og = t & 7, eg = t >> 3;
#pragma unroll
    for (int e = 0; e < 4; e++) {
        int ei = eg * 4 + e;
        if (ei < nvalid) {
            float2 f0 = unpack2(acc[e][0]), f1 = unpack2(acc[e][1]);
            float2 f2 = unpack2(acc[e][2]), f3 = unpack2(acc[e][3]);
            float4 o0, o1;
            o0.x = gelu_f(f0.x); o0.y = gelu_f(f0.y);
            o0.z = gelu_f(f1.x); o0.w = gelu_f(f1.y);
            o1.x = gelu_f(f2.x); o1.y = gelu_f(f2.y);
            o1.z = gelu_f(f3.x); o1.w = gelu_f(f3.y);
            float4* op = (float4*)(g_msg + (size_t)(n0 + ei) * 64 + og * 8);
            op[0] = o0;
            op[1] = o1;
        }
    }
}

// gate epilogue: er2 = gelu(acc); gather M[dst]; scatter red.add to g_agg[src]
__device__ __forceinline__ void gemm_gate(const float* __restrict__ sIn,
                                          const float* __restrict__ sW,
                                          const float* __restrict__ sbias,
                                          const int* __restrict__ sSrc,
                                          const int* __restrict__ sDst,
                                          int nvalid, int t)
{
    ull acc[4][4];
    gemm_acc(sIn, sW, sbias, t, acc);
    int og = t & 7, eg = t >> 3;
#pragma unroll
    for (int e = 0; e < 4; e++) {
        int ei = eg * 4 + e;
        if (ei < nvalid) {
            float2 f0 = unpack2(acc[e][0]), f1 = unpack2(acc[e][1]);
            float2 f2 = unpack2(acc[e][2]), f3 = unpack2(acc[e][3]);
            float g0 = gelu_f(f0.x), g1 = gelu_f(f0.y);
            float g2 = gelu_f(f1.x), g3 = gelu_f(f1.y);
            float g4 = gelu_f(f2.x), g5 = gelu_f(f2.y);
            float g6 = gelu_f(f3.x), g7 = gelu_f(f3.y);
            const float4* mp =
                (const float4*)(g_msg + (size_t)sDst[ei] * 64 + og * 8);
            float4 m0 = __ldg(mp);
            float4 m1 = __ldg(mp + 1);
            float* ap = g_agg + (size_t)sSrc[ei] * 64 + og * 8;
            red_add_v4(ap,     m0.x * g0, m0.y * g1, m0.z * g2, m0.w * g3);
            red_add_v4(ap + 4, m1.x * g4, m1.y * g5, m1.z * g6, m1.w * g7);
        }
    }
}

// ---------------- msg kernel: per-node message MLP precompute ----------------
// smem floats: Wm1 4096 | Wm2 4096 | sb 128 | A 8704 | B 8704 = 25728 (~103KB)
#define MSG_SMTOT 25728
__global__ void __launch_bounds__(256, 2)
msg_kernel(const float* __restrict__ nf, int N)
{
    extern __shared__ float sm[];
    float* sW1 = sm;
    float* sW2 = sm + 4096;
    float* sb  = sm + 8192;
    float* sA  = sm + 8320;
    float* sB  = sm + 8320 + 8704;

    int t = threadIdx.x;
    int n0 = blockIdx.x * 128;
    int nvalid = min(128, N - n0);
    unsigned sbase = (unsigned)__cvta_generic_to_shared(sm);

    for (int i = t; i < 2048; i += 256) {
        int r = i >> 4, q = i & 15;
        int rr = (r < nvalid) ? r : 0;
        cp_async16(sbase + (8320 + r * ROWP + q * 4) * 4,
                   nf + (size_t)(n0 + rr) * 64 + q * 4);
    }
    asm volatile("cp.async.commit_group;" ::: "memory");

    for (int i = t; i < 1024; i += 256) {
        ((float4*)sW1)[i] = ((const float4*)g_Wm1)[i];
        ((float4*)sW2)[i] = ((const float4*)g_Wm2)[i];
    }
    if (t < 64) {
        sb[t]      = g_cm1[t];
        sb[64 + t] = g_cm2[t];
    }
    asm volatile("cp.async.wait_group 0;" ::: "memory");
    __syncthreads();
    gemm_tile(sA, sW1, sb, sB, t);
    __syncthreads();
    gemm_out(sB, sW2, sb + 64, n0, nvalid, t);
}

// ---------------- edge kernel: edge MLP + gate + scatter ----------------
// smem floats: We1 4096 | We2 4096 | sb 128 | src 128 | dst 128 | A 8704 | B 8704
//  = 25984 floats (~104KB) -> 2 blocks/SM
#define EG_SB   8192
#define EG_SRC  8320
#define EG_DST  8448
#define EG_A    8576
#define EG_B    (8576 + 8704)
#define EG_SMTOT (8576 + 2 * 8704)

__global__ void __launch_bounds__(256, 2)
edge_kernel(const float* __restrict__ ef,
            const int* __restrict__ src, const int* __restrict__ dst,
            const float* __restrict__ We1, const float* __restrict__ ce1,
            const float* __restrict__ We2, const float* __restrict__ ce2,
            int E)
{
    extern __shared__ float sm[];
    float* sW1 = sm;
    float* sW2 = sm + 4096;
    float* sb  = sm + EG_SB;
    int* sSrc  = (int*)(sm + EG_SRC);
    int* sDst  = (int*)(sm + EG_DST);
    float* sA  = sm + EG_A;
    float* sB  = sm + EG_B;

    int t = threadIdx.x;
    int e0 = blockIdx.x * 128;
    int nvalid = min(128, E - e0);
    unsigned sbase = (unsigned)__cvta_generic_to_shared(sm);

    // stream edge features -> sA
    for (int i = t; i < 2048; i += 256) {
        int e = i >> 4, q = i & 15;
        int ee = (e < nvalid) ? e : 0;
        cp_async16(sbase + (EG_A + e * ROWP + q * 4) * 4,
                   ef + (size_t)(e0 + ee) * 64 + q * 4);
    }
    asm volatile("cp.async.commit_group;" ::: "memory");

    for (int i = t; i < 1024; i += 256) {
        ((float4*)sW1)[i] = __ldg((const float4*)We1 + i);
        ((float4*)sW2)[i] = __ldg((const float4*)We2 + i);
    }
    if (t < 64) {
        sb[t]      = __ldg(ce1 + t);
        sb[64 + t] = __ldg(ce2 + t);
    }
    if (t < 128) {
        sSrc[t] = (t < nvalid) ? src[e0 + t] : 0;
        sDst[t] = (t < nvalid) ? dst[e0 + t] : 0;
    }
    asm volatile("cp.async.wait_group 0;" ::: "memory");
    __syncthreads();
    gemm_tile(sA, sW1, sb, sB, t);        // ef -> er1
    __syncthreads();
    gemm_gate(sB, sW2, sb + 64, sSrc, sDst, nvalid, t);  // gate + scatter

    if ((t & 7) == 0) {
        int eg = t >> 3;
#pragma unroll
        for (int e = 0; e < 4; e++) {
            int ei = eg * 4 + e;
            if (ei < nvalid) atomicAdd(&g_cnt[sSrc[ei]], 1.0f);
        }
    }
}

// ---------------- node kernel: mean + update MLP ----------------
__global__ void __launch_bounds__(128, 2)
node_kernel(const float* __restrict__ nf, float* __restrict__ out, int N)
{
    extern __shared__ float sm[];
    float* sW1 = sm;
    float* sW2 = sm + 8192;
    float* sb  = sm + 12288;
    float* io  = sm + 12416;

    for (int i = threadIdx.x; i < 8192; i += 128) sW1[i] = g_Wu1[i];
    for (int i = threadIdx.x; i < 4096; i += 128) sW2[i] = g_Wu2[i];
    if (threadIdx.x < 64) {
        sb[threadIdx.x]      = g_cu1[threadIdx.x];
        sb[64 + threadIdx.x] = g_cu2[threadIdx.x];
    }
    __syncthreads();

    int n = blockIdx.x * 128 + threadIdx.x;
    if (n >= N) return;

    float x[128];
    const float4* nrow = (const float4*)(nf + (size_t)n * 64);
#pragma unroll
    for (int k = 0; k < 16; k++) {
        float4 v = __ldg(nrow + k);
        x[4 * k + 0] = v.x; x[4 * k + 1] = v.y;
        x[4 * k + 2] = v.z; x[4 * k + 3] = v.w;
    }
    float c = g_cnt[n];
    float inv = 1.0f / fmaxf(c, 1.0f);
    const float4* arow = (const float4*)(g_agg + (size_t)n * 64);
#pragma unroll
    for (int k = 0; k < 16; k++) {
        float4 v = arow[k];
        x[64 + 4 * k + 0] = v.x * inv; x[64 + 4 * k + 1] = v.y * inv;
        x[64 + 4 * k + 2] = v.z * inv; x[64 + 4 * k + 3] = v.w * inv;
    }

    float* col = io + threadIdx.x;
#pragma unroll 1
    for (int q = 0; q < 16; q++) {
        const ulonglong2* bp = (const ulonglong2*)(sb + q * 4);
        ulonglong2 bb = bp[0];
        ull a0 = bb.x, a1 = bb.y;
        const float* wp = sW1 + q * 4;
#pragma unroll
        for (int k = 0; k < 128; k++) {
            ull xx = pack2(x[k]);
            ulonglong2 w = *(const ulonglong2*)(wp + k * 64);
            a0 = fma2(xx, w.x, a0);
            a1 = fma2(xx, w.y, a1);
        }
        float2 f0 = unpack2(a0), f1 = unpack2(a1);
        col[(q * 4 + 0) * 128] = gelu_f(f0.x);
        col[(q * 4 + 1) * 128] = gelu_f(f0.y);
        col[(q * 4 + 2) * 128] = gelu_f(f1.x);
        col[(q * 4 + 3) * 128] = gelu_f(f1.y);
    }
#pragma unroll
    for (int k = 0; k < 64; k++) x[k] = col[k * 128];
    float4* orow = (float4*)(out + (size_t)n * 64);
#pragma unroll 1
    for (int q = 0; q < 16; q++) {
        const ulonglong2* bp = (const ulonglong2*)(sb + 64 + q * 4);
        ulonglong2 bb = bp[0];
        ull a0 = bb.x, a1 = bb.y;
        const float* wp = sW2 + q * 4;
#pragma unroll
        for (int k = 0; k < 64; k++) {
            ull xx = pack2(x[k]);
            ulonglong2 w = *(const ulonglong2*)(wp + k * 64);
            a0 = fma2(xx, w.x, a0);
            a1 = fma2(xx, w.y, a1);
        }
        float2 f0 = unpack2(a0), f1 = unpack2(a1);
        float4 o;
        o.x = gelu_f(f0.x); o.y = gelu_f(f0.y);
        o.z = gelu_f(f1.x); o.w = gelu_f(f1.y);
        orow[q] = o;
    }
}

// ---------------- launch ----------------
extern "C" void kernel_launch(void* const* d_in, const int* in_sizes, int n_in,
                              void* d_out, int out_size)
{
    bool dictOrder = (in_sizes[2] > 64);
    const float* nf = (const float*)d_in[0];
    const float* ef = (const float*)d_in[1];
    const int* src = (const int*)d_in[dictOrder ? 2 : 30];
    const int* dst = (const int*)d_in[dictOrder ? 3 : 31];
    int p0 = dictOrder ? 4 : 2;
    const float* P[28];
    for (int i = 0; i < 28; i++) P[i] = (const float*)d_in[p0 + i];

    int E = in_sizes[1] / 64;
    int N = in_sizes[0] / 64;

    cudaFuncSetAttribute(msg_kernel, cudaFuncAttributeMaxDynamicSharedMemorySize,
                         MSG_SMTOT * (int)sizeof(float));
    cudaFuncSetAttribute(edge_kernel, cudaFuncAttributeMaxDynamicSharedMemorySize,
                         EG_SMTOT * (int)sizeof(float));
    cudaFuncSetAttribute(node_kernel, cudaFuncAttributeMaxDynamicSharedMemorySize,
                         20608 * (int)sizeof(float));

    fold_kernel<<<(20736 + 255) / 256, 256>>>(
        P[0], P[1], P[2], P[3], P[4], P[5], P[6], P[7], P[8], P[9], P[10], P[11],
        P[16], P[17], P[18], P[19], P[20], P[21], P[22], P[23], P[24], P[25], P[26], P[27]);
    zero_kernel<<<2048, 256>>>();
    msg_kernel<<<(N + 127) / 128, 256, MSG_SMTOT * sizeof(float)>>>(nf, N);
    edge_kernel<<<(E + 127) / 128, 256, EG_SMTOT * sizeof(float)>>>(
        ef, src, dst, P[12], P[13], P[14], P[15], E);
    node_kernel<<<(N + 127) / 128, 128, 20608 * sizeof(float)>>>(
        nf, (float*)d_out, N);
}

// round 7
// speedup vs baseline: 3.2922x; 1.3550x over previous
#include <cuda_runtime.h>
#include <cuda_bf16.h>
#include <math.h>

#define NODES 50000
#define DF 64
#define HF 64
#define BN_EPS 1e-3f
#define ROWP 68

typedef unsigned long long ull;

// ---------------- device scratch (static, no allocs) ----------------
__device__ float g_Wm1[DF * HF];
__device__ float g_cm1[HF];
__device__ float g_Wm2[HF * HF];
__device__ float g_cm2[HF];
__device__ float g_Wu1[(DF + HF) * HF];
__device__ float g_cu1[HF];
__device__ float g_Wu2[HF * HF];
__device__ float g_cu2[HF];
__device__ float g_agg[(size_t)NODES * HF];   // segment sums
__device__ float g_cnt[NODES];                // segment counts
__device__ float g_msg[(size_t)NODES * HF];   // per-node precomputed message
__device__ float4 g_We1p[2048];               // packed tf32 split of e_W1
__device__ float4 g_We2p[2048];               // packed tf32 split of e_W2

// ---------------- helpers ----------------
__device__ __forceinline__ float gelu_f(float v) {
    return 0.5f * v * (1.0f + erff(v * 0.70710678118654752440f));
}
__device__ __forceinline__ ull pack2(float v) {
    ull r;
    asm("mov.b64 %0, {%1, %1};" : "=l"(r) : "f"(v));
    return r;
}
__device__ __forceinline__ ull fma2(ull a, ull b, ull c) {
    ull d;
    asm("fma.rn.f32x2 %0, %1, %2, %3;" : "=l"(d) : "l"(a), "l"(b), "l"(c));
    return d;
}
__device__ __forceinline__ float2 unpack2(ull v) {
    float2 f;
    asm("mov.b64 {%0, %1}, %2;" : "=f"(f.x), "=f"(f.y) : "l"(v));
    return f;
}
__device__ __forceinline__ void red_add_v4(float* p, float a, float b, float c, float d) {
    asm volatile("red.global.add.v4.f32 [%0], {%1, %2, %3, %4};"
                 :: "l"(p), "f"(a), "f"(b), "f"(c), "f"(d) : "memory");
}
__device__ __forceinline__ void red_add_v2(float* p, float a, float b) {
    asm volatile("red.global.add.v2.f32 [%0], {%1, %2};"
                 :: "l"(p), "f"(a), "f"(b) : "memory");
}
__device__ __forceinline__ void cp_async16(unsigned saddr, const void* gptr) {
    asm volatile("cp.async.cg.shared.global [%0], [%1], 16;" :: "r"(saddr), "l"(gptr));
}
__device__ __forceinline__ unsigned tf32r(float v) {
    unsigned r;
    asm("cvt.rna.tf32.f32 %0, %1;" : "=r"(r) : "f"(v));
    return r;
}
__device__ __forceinline__ void mma8(float c[4],
                                     unsigned a0, unsigned a1, unsigned a2, unsigned a3,
                                     unsigned b0, unsigned b1) {
    asm volatile("mma.sync.aligned.m16n8k8.row.col.f32.tf32.tf32.f32 "
                 "{%0,%1,%2,%3}, {%4,%5,%6,%7}, {%8,%9}, {%0,%1,%2,%3};"
                 : "+f"(c[0]), "+f"(c[1]), "+f"(c[2]), "+f"(c[3])
                 : "r"(a0), "r"(a1), "r"(a2), "r"(a3), "r"(b0), "r"(b1));
}

// ---------------- fold kernel: BN -> weights ----------------
__global__ void fold_kernel(
    const float* __restrict__ m_g1, const float* __restrict__ m_b1,
    const float* __restrict__ m_mu1, const float* __restrict__ m_v1,
    const float* __restrict__ m_W1, const float* __restrict__ m_c1,
    const float* __restrict__ m_g2, const float* __restrict__ m_b2,
    const float* __restrict__ m_mu2, const float* __restrict__ m_v2,
    const float* __restrict__ m_W2, const float* __restrict__ m_c2,
    const float* __restrict__ u_g1, const float* __restrict__ u_b1,
    const float* __restrict__ u_mu1, const float* __restrict__ u_v1,
    const float* __restrict__ u_W1, const float* __restrict__ u_c1,
    const float* __restrict__ u_g2, const float* __restrict__ u_b2,
    const float* __restrict__ u_mu2, const float* __restrict__ u_v2,
    const float* __restrict__ u_W2, const float* __restrict__ u_c2)
{
    int t = blockIdx.x * blockDim.x + threadIdx.x;
    if (t < 4096) {
        int k = t >> 6;
        float s = m_g1[k] * rsqrtf(m_v1[k] + BN_EPS);
        g_Wm1[t] = s * m_W1[t];
    } else if (t < 8192) {
        int i = t - 4096; int k = i >> 6;
        float s = m_g2[k] * rsqrtf(m_v2[k] + BN_EPS);
        g_Wm2[i] = s * m_W2[i];
    } else if (t < 16384) {
        int i = t - 8192; int k = i >> 6;
        float s = u_g1[k] * rsqrtf(u_v1[k] + BN_EPS);
        g_Wu1[i] = s * u_W1[i];
    } else if (t < 20480) {
        int i = t - 16384; int k = i >> 6;
        float s = u_g2[k] * rsqrtf(u_v2[k] + BN_EPS);
        g_Wu2[i] = s * u_W2[i];
    } else if (t < 20544) {
        int j = t - 20480;
        float sum = m_c1[j];
        for (int k = 0; k < DF; k++) {
            float s = m_g1[k] * rsqrtf(m_v1[k] + BN_EPS);
            sum += (m_b1[k] - m_mu1[k] * s) * m_W1[k * HF + j];
        }
        g_cm1[j] = sum;
    } else if (t < 20608) {
        int j = t - 20544;
        float sum = m_c2[j];
        for (int k = 0; k < HF; k++) {
            float s = m_g2[k] * rsqrtf(m_v2[k] + BN_EPS);
            sum += (m_b2[k] - m_mu2[k] * s) * m_W2[k * HF + j];
        }
        g_cm2[j] = sum;
    } else if (t < 20672) {
        int j = t - 20608;
        float sum = u_c1[j];
        for (int k = 0; k < DF + HF; k++) {
            float s = u_g1[k] * rsqrtf(u_v1[k] + BN_EPS);
            sum += (u_b1[k] - u_mu1[k] * s) * u_W1[k * HF + j];
        }
        g_cu1[j] = sum;
    } else if (t < 20736) {
        int j = t - 20672;
        float sum = u_c2[j];
        for (int k = 0; k < HF; k++) {
            float s = u_g2[k] * rsqrtf(u_v2[k] + BN_EPS);
            sum += (u_b2[k] - u_mu2[k] * s) * u_W2[k * HF + j];
        }
        g_cu2[j] = sum;
    }
}

// ---------------- pack kernel: tf32 hi/lo split of edge weights ----------------
// Layout: P[kt*256 + n*4 + r] = (hi(W[8kt+r][n]), hi(W[8kt+r+4][n]),
//                                lo(W[8kt+r][n]), lo(W[8kt+r+4][n]))
// (n-major within kt so B-fragment LDS.128 is phase-conflict-free)
__global__ void pack_kernel(const float* __restrict__ We1, const float* __restrict__ We2) {
    int t = blockIdx.x * blockDim.x + threadIdx.x;
    if (t >= 4096) return;
    const float* W = (t & 2048) ? We2 : We1;
    float4* P = (t & 2048) ? g_We2p : g_We1p;
    int i = t & 2047;
    int kt = i >> 8, rem = i & 255, n = rem >> 2, r = rem & 3;
    float w1 = W[(kt * 8 + r) * 64 + n];
    float w2 = W[(kt * 8 + r + 4) * 64 + n];
    unsigned h1 = tf32r(w1), h2 = tf32r(w2);
    float4 o;
    o.x = __uint_as_float(h1);
    o.y = __uint_as_float(h2);
    o.z = __uint_as_float(tf32r(w1 - __uint_as_float(h1)));
    o.w = __uint_as_float(tf32r(w2 - __uint_as_float(h2)));
    P[i] = o;
}

// ---------------- zero accumulators ----------------
__global__ void zero_kernel() {
    size_t total = (size_t)NODES * HF;
    for (size_t i = blockIdx.x * (size_t)blockDim.x + threadIdx.x;
         i < total; i += (size_t)gridDim.x * blockDim.x) {
        g_agg[i] = 0.0f;
        if (i < NODES) g_cnt[i] = 0.0f;
    }
}

// =====================================================================
// FFMA2 register-tiled GEMM helpers (used by msg_kernel)
// =====================================================================
__device__ __forceinline__ void gemm_acc(const float* __restrict__ sIn,
                                         const float* __restrict__ sW,
                                         const float* __restrict__ sbias,
                                         int t, ull acc[4][4])
{
    int og = t & 7, eg = t >> 3;
    const float* xin = sIn + eg * 4 * ROWP;
    {
        const ulonglong2* bp = (const ulonglong2*)(sbias + og * 8);
        ulonglong2 b0 = bp[0], b1 = bp[1];
#pragma unroll
        for (int e = 0; e < 4; e++) {
            acc[e][0] = b0.x; acc[e][1] = b0.y;
            acc[e][2] = b1.x; acc[e][3] = b1.y;
        }
    }
#pragma unroll
    for (int kc = 0; kc < 16; kc++) {
        float4 xv[4];
#pragma unroll
        for (int e = 0; e < 4; e++)
            xv[e] = *(const float4*)(xin + e * ROWP + kc * 4);
#pragma unroll
        for (int kk = 0; kk < 4; kk++) {
            const ulonglong2* wp =
                (const ulonglong2*)(sW + (kc * 4 + kk) * 64 + og * 8);
            ulonglong2 wa = wp[0], wb = wp[1];
#pragma unroll
            for (int e = 0; e < 4; e++) {
                float xs = (kk == 0) ? xv[e].x : (kk == 1) ? xv[e].y
                         : (kk == 2) ? xv[e].z : xv[e].w;
                ull xx = pack2(xs);
                acc[e][0] = fma2(xx, wa.x, acc[e][0]);
                acc[e][1] = fma2(xx, wa.y, acc[e][1]);
                acc[e][2] = fma2(xx, wb.x, acc[e][2]);
                acc[e][3] = fma2(xx, wb.y, acc[e][3]);
            }
        }
    }
}

__device__ __forceinline__ void gemm_tile(const float* __restrict__ sIn,
                                          const float* __restrict__ sW,
                                          const float* __restrict__ sbias,
                                          float* __restrict__ sOut, int t)
{
    ull acc[4][4];
    gemm_acc(sIn, sW, sbias, t, acc);
    int og = t & 7, eg = t >> 3;
#pragma unroll
    for (int e = 0; e < 4; e++) {
        float2 f0 = unpack2(acc[e][0]), f1 = unpack2(acc[e][1]);
        float2 f2 = unpack2(acc[e][2]), f3 = unpack2(acc[e][3]);
        float4 o0, o1;
        o0.x = gelu_f(f0.x); o0.y = gelu_f(f0.y);
        o0.z = gelu_f(f1.x); o0.w = gelu_f(f1.y);
        o1.x = gelu_f(f2.x); o1.y = gelu_f(f2.y);
        o1.z = gelu_f(f3.x); o1.w = gelu_f(f3.y);
        float* op = sOut + (eg * 4 + e) * ROWP + og * 8;
        *(float4*)op = o0;
        *(float4*)(op + 4) = o1;
    }
}

__device__ __forceinline__ void gemm_out(const float* __restrict__ sIn,
                                         const float* __restrict__ sW,
                                         const float* __restrict__ sbias,
                                         int n0, int nvalid, int t)
{
    ull acc[4][4];
    gemm_acc(sIn, sW, sbias, t, acc);
    int og = t & 7, eg = t >> 3;
#pragma unroll
    for (int e = 0; e < 4; e++) {
        int ei = eg * 4 + e;
        if (ei < nvalid) {
            float2 f0 = unpack2(acc[e][0]), f1 = unpack2(acc[e][1]);
            float2 f2 = unpack2(acc[e][2]), f3 = unpack2(acc[e][3]);
            float4 o0, o1;
            o0.x = gelu_f(f0.x); o0.y = gelu_f(f0.y);
            o0.z = gelu_f(f1.x); o0.w = gelu_f(f1.y);
            o1.x = gelu_f(f2.x); o1.y = gelu_f(f2.y);
            o1.z = gelu_f(f3.x); o1.w = gelu_f(f3.y);
            float4* op = (float4*)(g_msg + (size_t)(n0 + ei) * 64 + og * 8);
            op[0] = o0;
            op[1] = o1;
        }
    }
}

// ---------------- msg kernel: per-node message MLP precompute ----------------
#define MSG_SMTOT 25728
__global__ void __launch_bounds__(256, 2)
msg_kernel(const float* __restrict__ nf, int N)
{
    extern __shared__ float sm[];
    float* sW1 = sm;
    float* sW2 = sm + 4096;
    float* sb  = sm + 8192;
    float* sA  = sm + 8320;
    float* sB  = sm + 8320 + 8704;

    int t = threadIdx.x;
    int n0 = blockIdx.x * 128;
    int nvalid = min(128, N - n0);
    unsigned sbase = (unsigned)__cvta_generic_to_shared(sm);

    for (int i = t; i < 2048; i += 256) {
        int r = i >> 4, q = i & 15;
        int rr = (r < nvalid) ? r : 0;
        cp_async16(sbase + (8320 + r * ROWP + q * 4) * 4,
                   nf + (size_t)(n0 + rr) * 64 + q * 4);
    }
    asm volatile("cp.async.commit_group;" ::: "memory");

    for (int i = t; i < 1024; i += 256) {
        ((float4*)sW1)[i] = ((const float4*)g_Wm1)[i];
        ((float4*)sW2)[i] = ((const float4*)g_Wm2)[i];
    }
    if (t < 64) {
        sb[t]      = g_cm1[t];
        sb[64 + t] = g_cm2[t];
    }
    asm volatile("cp.async.wait_group 0;" ::: "memory");
    __syncthreads();
    gemm_tile(sA, sW1, sb, sB, t);
    __syncthreads();
    gemm_out(sB, sW2, sb + 64, n0, nvalid, t);
}

// =====================================================================
// Edge kernel: tf32 mma.sync 3-pass (fp32-accurate) edge MLP + gate + scatter
// 256 threads = 8 warps; warp w owns edge rows [16w, 16w+16) of a 128-edge tile.
// smem floats: sW1p 8192 | sW2p 8192 | sb 128 | sA 128*68 = 8704  -> 25216 (~101KB)
// =====================================================================
#define ESM_W2 8192
#define ESM_B  16384
#define ESM_A  16512
#define ESM_TOT (16512 + 128 * ROWP)

__global__ void __launch_bounds__(256, 2)
edge_kernel(const float* __restrict__ ef,
            const int* __restrict__ src, const int* __restrict__ dst,
            const float* __restrict__ ce1, const float* __restrict__ ce2,
            int E)
{
    extern __shared__ float sm[];
    float* sW1 = sm;
    float* sW2 = sm + ESM_W2;
    float* sb  = sm + ESM_B;
    float* sA  = sm + ESM_A;

    int t = threadIdx.x;
    int w = t >> 5, l = t & 31;
    int lr = l >> 2, lc = l & 3;
    unsigned sbase = (unsigned)__cvta_generic_to_shared(sm);
    int ntiles = (E + 127) >> 7;

    // stage first tile
    if (blockIdx.x < ntiles) {
        int e0 = blockIdx.x << 7;
        for (int i = t; i < 2048; i += 256) {
            int e = i >> 4, q = i & 15;
            int ee = min(e0 + e, E - 1);
            cp_async16(sbase + (ESM_A + e * ROWP + q * 4) * 4,
                       ef + (size_t)ee * 64 + q * 4);
        }
    }
    asm volatile("cp.async.commit_group;" ::: "memory");

    // weights (pre-split tf32 hi/lo) + biases
    for (int i = t; i < 2048; i += 256) {
        ((float4*)sW1)[i] = g_We1p[i];
        ((float4*)sW2)[i] = g_We2p[i];
    }
    if (t < 64) {
        sb[t]      = __ldg(ce1 + t);
        sb[64 + t] = __ldg(ce2 + t);
    }

    float* As = sA + w * 16 * ROWP;   // warp's 16 edge rows

    for (int tile = blockIdx.x; tile < ntiles; tile += gridDim.x) {
        asm volatile("cp.async.wait_group 0;" ::: "memory");
        __syncthreads();
        int e0 = tile << 7;

        float acc[8][4];

        // ---------- GEMM1: er1 = gelu(ef @ We1 + c1), in place ----------
#pragma unroll
        for (int nt = 0; nt < 8; nt++) {
            float b0 = sb[nt * 8 + 2 * lc];
            float b1 = sb[nt * 8 + 2 * lc + 1];
            acc[nt][0] = b0; acc[nt][1] = b1; acc[nt][2] = b0; acc[nt][3] = b1;
        }
#pragma unroll
        for (int kt = 0; kt < 8; kt++) {
            float a0 = As[lr * ROWP + kt * 8 + lc];
            float a1 = As[(lr + 8) * ROWP + kt * 8 + lc];
            float a2 = As[lr * ROWP + kt * 8 + lc + 4];
            float a3 = As[(lr + 8) * ROWP + kt * 8 + lc + 4];
            unsigned h0 = tf32r(a0), h1 = tf32r(a1), h2 = tf32r(a2), h3 = tf32r(a3);
            unsigned lo0 = tf32r(a0 - __uint_as_float(h0));
            unsigned lo1 = tf32r(a1 - __uint_as_float(h1));
            unsigned lo2 = tf32r(a2 - __uint_as_float(h2));
            unsigned lo3 = tf32r(a3 - __uint_as_float(h3));
            const float4* wbase = (const float4*)sW1 + kt * 256 + lr * 4 + lc;
#pragma unroll
            for (int nt = 0; nt < 8; nt++) {
                float4 bq = wbase[nt * 32];   // (nt*8 rows of n) * 4
                unsigned bh0 = __float_as_uint(bq.x), bh1 = __float_as_uint(bq.y);
                unsigned bl0 = __float_as_uint(bq.z), bl1 = __float_as_uint(bq.w);
                mma8(acc[nt], h0, h1, h2, h3, bh0, bh1);
                mma8(acc[nt], lo0, lo1, lo2, lo3, bh0, bh1);
                mma8(acc[nt], h0, h1, h2, h3, bl0, bl1);
            }
        }
#pragma unroll
        for (int nt = 0; nt < 8; nt++) {
            float2 p0, p1;
            p0.x = gelu_f(acc[nt][0]); p0.y = gelu_f(acc[nt][1]);
            p1.x = gelu_f(acc[nt][2]); p1.y = gelu_f(acc[nt][3]);
            *(float2*)(As + lr * ROWP + nt * 8 + 2 * lc) = p0;
            *(float2*)(As + (lr + 8) * ROWP + nt * 8 + 2 * lc) = p1;
        }

        // ---------- GEMM2: er2 = er1 @ We2 + c2; gate + scatter ----------
#pragma unroll
        for (int nt = 0; nt < 8; nt++) {
            float b0 = sb[64 + nt * 8 + 2 * lc];
            float b1 = sb[64 + nt * 8 + 2 * lc + 1];
            acc[nt][0] = b0; acc[nt][1] = b1; acc[nt][2] = b0; acc[nt][3] = b1;
        }
#pragma unroll
        for (int kt = 0; kt < 8; kt++) {
            float a0 = As[lr * ROWP + kt * 8 + lc];
            float a1 = As[(lr + 8) * ROWP + kt * 8 + lc];
            float a2 = As[lr * ROWP + kt * 8 + lc + 4];
            float a3 = As[(lr + 8) * ROWP + kt * 8 + lc + 4];
            unsigned h0 = tf32r(a0), h1 = tf32r(a1), h2 = tf32r(a2), h3 = tf32r(a3);
            unsigned lo0 = tf32r(a0 - __uint_as_float(h0));
            unsigned lo1 = tf32r(a1 - __uint_as_float(h1));
            unsigned lo2 = tf32r(a2 - __uint_as_float(h2));
            unsigned lo3 = tf32r(a3 - __uint_as_float(h3));
            const float4* wbase = (const float4*)sW2 + kt * 256 + lr * 4 + lc;
#pragma unroll
            for (int nt = 0; nt < 8; nt++) {
                float4 bq = wbase[nt * 32];
                unsigned bh0 = __float_as_uint(bq.x), bh1 = __float_as_uint(bq.y);
                unsigned bl0 = __float_as_uint(bq.z), bl1 = __float_as_uint(bq.w);
                mma8(acc[nt], h0, h1, h2, h3, bh0, bh1);
                mma8(acc[nt], lo0, lo1, lo2, lo3, bh0, bh1);
                mma8(acc[nt], h0, h1, h2, h3, bl0, bl1);
            }
        }

        // epilogue: gelu, gather msg[dst], red.add to agg[src]
        int el1 = e0 + w * 16 + lr;
        int el2 = el1 + 8;
        bool v1 = el1 < E, v2 = el2 < E;
        int s1 = 0, d1 = 0, s2 = 0, d2 = 0;
        if (v1) { s1 = __ldg(src + el1); d1 = __ldg(dst + el1); }
        if (v2) { s2 = __ldg(src + el2); d2 = __ldg(dst + el2); }
#pragma unroll
        for (int nt = 0; nt < 8; nt++) {
            int col = nt * 8 + 2 * lc;
            if (v1) {
                float g0 = gelu_f(acc[nt][0]), g1 = gelu_f(acc[nt][1]);
                float2 m = __ldg((const float2*)(g_msg + (size_t)d1 * 64 + col));
                red_add_v2(g_agg + (size_t)s1 * 64 + col, m.x * g0, m.y * g1);
            }
            if (v2) {
                float g2 = gelu_f(acc[nt][2]), g3 = gelu_f(acc[nt][3]);
                float2 m = __ldg((const float2*)(g_msg + (size_t)d2 * 64 + col));
                red_add_v2(g_agg + (size_t)s2 * 64 + col, m.x * g2, m.y * g3);
            }
        }
        // per-edge counts
        if (t < 128) {
            int e = e0 + t;
            if (e < E) atomicAdd(&g_cnt[__ldg(src + e)], 1.0f);
        }

        __syncthreads();   // all reads of sA done before restage

        int nxt = tile + gridDim.x;
        if (nxt < ntiles) {
            int ne0 = nxt << 7;
            for (int i = t; i < 2048; i += 256) {
                int e = i >> 4, q = i & 15;
                int ee = min(ne0 + e, E - 1);
                cp_async16(sbase + (ESM_A + e * ROWP + q * 4) * 4,
                           ef + (size_t)ee * 64 + q * 4);
            }
        }
        asm volatile("cp.async.commit_group;" ::: "memory");
    }
}

// ---------------- node kernel: mean + update MLP ----------------
__global__ void __launch_bounds__(128, 2)
node_kernel(const float* __restrict__ nf, float* __restrict__ out, int N)
{
    extern __shared__ float sm[];
    float* sW1 = sm;
    float* sW2 = sm + 8192;
    float* sb  = sm + 12288;
    float* io  = sm + 12416;

    for (int i = threadIdx.x; i < 8192; i += 128) sW1[i] = g_Wu1[i];
    for (int i = threadIdx.x; i < 4096; i += 128) sW2[i] = g_Wu2[i];
    if (threadIdx.x < 64) {
        sb[threadIdx.x]      = g_cu1[threadIdx.x];
        sb[64 + threadIdx.x] = g_cu2[threadIdx.x];
    }
    __syncthreads();

    int n = blockIdx.x * 128 + threadIdx.x;
    if (n >= N) return;

    float x[128];
    const float4* nrow = (const float4*)(nf + (size_t)n * 64);
#pragma unroll
    for (int k = 0; k < 16; k++) {
        float4 v = __ldg(nrow + k);
        x[4 * k + 0] = v.x; x[4 * k + 1] = v.y;
        x[4 * k + 2] = v.z; x[4 * k + 3] = v.w;
    }
    float c = g_cnt[n];
    float inv = 1.0f / fmaxf(c, 1.0f);
    const float4* arow = (const float4*)(g_agg + (size_t)n * 64);
#pragma unroll
    for (int k = 0; k < 16; k++) {
        float4 v = arow[k];
        x[64 + 4 * k + 0] = v.x * inv; x[64 + 4 * k + 1] = v.y * inv;
        x[64 + 4 * k + 2] = v.z * inv; x[64 + 4 * k + 3] = v.w * inv;
    }

    float* col = io + threadIdx.x;
#pragma unroll 1
    for (int q = 0; q < 16; q++) {
        const ulonglong2* bp = (const ulonglong2*)(sb + q * 4);
        ulonglong2 bb = bp[0];
        ull a0 = bb.x, a1 = bb.y;
        const float* wp = sW1 + q * 4;
#pragma unroll
        for (int k = 0; k < 128; k++) {
            ull xx = pack2(x[k]);
            ulonglong2 wv = *(const ulonglong2*)(wp + k * 64);
            a0 = fma2(xx, wv.x, a0);
            a1 = fma2(xx, wv.y, a1);
        }
        float2 f0 = unpack2(a0), f1 = unpack2(a1);
        col[(q * 4 + 0) * 128] = gelu_f(f0.x);
        col[(q * 4 + 1) * 128] = gelu_f(f0.y);
        col[(q * 4 + 2) * 128] = gelu_f(f1.x);
        col[(q * 4 + 3) * 128] = gelu_f(f1.y);
    }
#pragma unroll
    for (int k = 0; k < 64; k++) x[k] = col[k * 128];
    float4* orow = (float4*)(out + (size_t)n * 64);
#pragma unroll 1
    for (int q = 0; q < 16; q++) {
        const ulonglong2* bp = (const ulonglong2*)(sb + 64 + q * 4);
        ulonglong2 bb = bp[0];
        ull a0 = bb.x, a1 = bb.y;
        const float* wp = sW2 + q * 4;
#pragma unroll
        for (int k = 0; k < 64; k++) {
            ull xx = pack2(x[k]);
            ulonglong2 wv = *(const ulonglong2*)(wp + k * 64);
            a0 = fma2(xx, wv.x, a0);
            a1 = fma2(xx, wv.y, a1);
        }
        float2 f0 = unpack2(a0), f1 = unpack2(a1);
        float4 o;
        o.x = gelu_f(f0.x); o.y = gelu_f(f0.y);
        o.z = gelu_f(f1.x); o.w = gelu_f(f1.y);
        orow[q] = o;
    }
}

// ---------------- launch ----------------
extern "C" void kernel_launch(void* const* d_in, const int* in_sizes, int n_in,
                              void* d_out, int out_size)
{
    bool dictOrder = (in_sizes[2] > 64);
    const float* nf = (const float*)d_in[0];
    const float* ef = (const float*)d_in[1];
    const int* src = (const int*)d_in[dictOrder ? 2 : 30];
    const int* dst = (const int*)d_in[dictOrder ? 3 : 31];
    int p0 = dictOrder ? 4 : 2;
    const float* P[28];
    for (int i = 0; i < 28; i++) P[i] = (const float*)d_in[p0 + i];

    int E = in_sizes[1] / 64;
    int N = in_sizes[0] / 64;

    cudaFuncSetAttribute(msg_kernel, cudaFuncAttributeMaxDynamicSharedMemorySize,
                         MSG_SMTOT * (int)sizeof(float));
    cudaFuncSetAttribute(edge_kernel, cudaFuncAttributeMaxDynamicSharedMemorySize,
                         ESM_TOT * (int)sizeof(float));
    cudaFuncSetAttribute(node_kernel, cudaFuncAttributeMaxDynamicSharedMemorySize,
                         20608 * (int)sizeof(float));

    fold_kernel<<<(20736 + 255) / 256, 256>>>(
        P[0], P[1], P[2], P[3], P[4], P[5], P[6], P[7], P[8], P[9], P[10], P[11],
        P[16], P[17], P[18], P[19], P[20], P[21], P[22], P[23], P[24], P[25], P[26], P[27]);
    pack_kernel<<<16, 256>>>(P[12], P[14]);
    zero_kernel<<<2048, 256>>>();
    msg_kernel<<<(N + 127) / 128, 256, MSG_SMTOT * sizeof(float)>>>(nf, N);
    edge_kernel<<<296, 256, ESM_TOT * sizeof(float)>>>(
        ef, src, dst, P[13], P[15], E);
    node_kernel<<<(N + 127) / 128, 128, 20608 * sizeof(float)>>>(
        nf, (float*)d_out, N);
}

// round 9
// speedup vs baseline: 3.9544x; 1.2011x over previous
#include <cuda_runtime.h>
#include <cuda_bf16.h>
#include <math.h>

#define NODES 50000
#define DF 64
#define HF 64
#define BN_EPS 1e-3f
#define ROWP 68
#define ROWP2 132

typedef unsigned long long ull;

// ---------------- device scratch (static, no allocs) ----------------
__device__ float g_Wm1[DF * HF];
__device__ float g_cm1[HF];
__device__ float g_Wm2[HF * HF];
__device__ float g_cm2[HF];
__device__ float g_Wu1[(DF + HF) * HF];
__device__ float g_cu1[HF];
__device__ float g_Wu2[HF * HF];
__device__ float g_cu2[HF];
__device__ float g_agg[(size_t)NODES * HF];   // segment sums
__device__ float g_cnt[NODES];                // segment counts
__device__ float g_msg[(size_t)NODES * HF];   // per-node precomputed message
// packed tf32 hi/lo weights: P[kt*256 + n*4 + r] =
//   (hi W[8kt+r][n], hi W[8kt+r+4][n], lo W[8kt+r][n], lo W[8kt+r+4][n])
__device__ float4 g_We1p[2048];
__device__ float4 g_We2p[2048];
__device__ float4 g_Wm1p[2048];
__device__ float4 g_Wm2p[2048];
__device__ float4 g_Wu1p[4096];   // K=128
__device__ float4 g_Wu2p[2048];

// ---------------- helpers ----------------
__device__ __forceinline__ float gelu_f(float v) {
    return 0.5f * v * (1.0f + erff(v * 0.70710678118654752440f));
}
__device__ __forceinline__ void red_add_v2(float* p, float a, float b) {
    asm volatile("red.global.add.v2.f32 [%0], {%1, %2};"
                 :: "l"(p), "f"(a), "f"(b) : "memory");
}
__device__ __forceinline__ void cp_async16(unsigned saddr, const void* gptr) {
    asm volatile("cp.async.cg.shared.global [%0], [%1], 16;" :: "r"(saddr), "l"(gptr));
}
__device__ __forceinline__ unsigned tf32r(float v) {
    unsigned r;
    asm("cvt.rna.tf32.f32 %0, %1;" : "=r"(r) : "f"(v));
    return r;
}
__device__ __forceinline__ void mma8(float c[4],
                                     unsigned a0, unsigned a1, unsigned a2, unsigned a3,
                                     unsigned b0, unsigned b1) {
    asm volatile("mma.sync.aligned.m16n8k8.row.col.f32.tf32.tf32.f32 "
                 "{%0,%1,%2,%3}, {%4,%5,%6,%7}, {%8,%9}, {%0,%1,%2,%3};"
                 : "+f"(c[0]), "+f"(c[1]), "+f"(c[2]), "+f"(c[3])
                 : "r"(a0), "r"(a1), "r"(a2), "r"(a3), "r"(b0), "r"(b1));
}

// =====================================================================
// Warp GEMM: 16 rows x 64 cols, K = KT*8, A in smem (row stride RP),
// W packed float4 hi/lo in smem, 2-pass tf32 (A-hi only; W = hi + lo).
// =====================================================================
template <int KT, int RP>
__device__ __forceinline__ void wgemm16(const float* __restrict__ As,
                                        const float4* __restrict__ Wp,
                                        const float* __restrict__ bias,
                                        int lr, int lc, float acc[8][4])
{
#pragma unroll
    for (int nt = 0; nt < 8; nt++) {
        float b0 = bias[nt * 8 + 2 * lc];
        float b1 = bias[nt * 8 + 2 * lc + 1];
        acc[nt][0] = b0; acc[nt][1] = b1; acc[nt][2] = b0; acc[nt][3] = b1;
    }
#pragma unroll
    for (int kt = 0; kt < KT; kt++) {
        float a0 = As[lr * RP + kt * 8 + lc];
        float a1 = As[(lr + 8) * RP + kt * 8 + lc];
        float a2 = As[lr * RP + kt * 8 + lc + 4];
        float a3 = As[(lr + 8) * RP + kt * 8 + lc + 4];
        unsigned h0 = tf32r(a0), h1 = tf32r(a1), h2 = tf32r(a2), h3 = tf32r(a3);
        const float4* wb = Wp + kt * 256 + lr * 4 + lc;
#pragma unroll
        for (int nt = 0; nt < 8; nt++) {
            float4 bq = wb[nt * 32];
            mma8(acc[nt], h0, h1, h2, h3,
                 __float_as_uint(bq.x), __float_as_uint(bq.y));
            mma8(acc[nt], h0, h1, h2, h3,
                 __float_as_uint(bq.z), __float_as_uint(bq.w));
        }
    }
}

// ---------------- fold kernel: BN -> weights ----------------
__global__ void fold_kernel(
    const float* __restrict__ m_g1, const float* __restrict__ m_b1,
    const float* __restrict__ m_mu1, const float* __restrict__ m_v1,
    const float* __restrict__ m_W1, const float* __restrict__ m_c1,
    const float* __restrict__ m_g2, const float* __restrict__ m_b2,
    const float* __restrict__ m_mu2, const float* __restrict__ m_v2,
    const float* __restrict__ m_W2, const float* __restrict__ m_c2,
    const float* __restrict__ u_g1, const float* __restrict__ u_b1,
    const float* __restrict__ u_mu1, const float* __restrict__ u_v1,
    const float* __restrict__ u_W1, const float* __restrict__ u_c1,
    const float* __restrict__ u_g2, const float* __restrict__ u_b2,
    const float* __restrict__ u_mu2, const float* __restrict__ u_v2,
    const float* __restrict__ u_W2, const float* __restrict__ u_c2)
{
    int t = blockIdx.x * blockDim.x + threadIdx.x;
    if (t < 4096) {
        int k = t >> 6;
        float s = m_g1[k] * rsqrtf(m_v1[k] + BN_EPS);
        g_Wm1[t] = s * m_W1[t];
    } else if (t < 8192) {
        int i = t - 4096; int k = i >> 6;
        float s = m_g2[k] * rsqrtf(m_v2[k] + BN_EPS);
        g_Wm2[i] = s * m_W2[i];
    } else if (t < 16384) {
        int i = t - 8192; int k = i >> 6;
        float s = u_g1[k] * rsqrtf(u_v1[k] + BN_EPS);
        g_Wu1[i] = s * u_W1[i];
    } else if (t < 20480) {
        int i = t - 16384; int k = i >> 6;
        float s = u_g2[k] * rsqrtf(u_v2[k] + BN_EPS);
        g_Wu2[i] = s * u_W2[i];
    } else if (t < 20544) {
        int j = t - 20480;
        float sum = m_c1[j];
        for (int k = 0; k < DF; k++) {
            float s = m_g1[k] * rsqrtf(m_v1[k] + BN_EPS);
            sum += (m_b1[k] - m_mu1[k] * s) * m_W1[k * HF + j];
        }
        g_cm1[j] = sum;
    } else if (t < 20608) {
        int j = t - 20544;
        float sum = m_c2[j];
        for (int k = 0; k < HF; k++) {
            float s = m_g2[k] * rsqrtf(m_v2[k] + BN_EPS);
            sum += (m_b2[k] - m_mu2[k] * s) * m_W2[k * HF + j];
        }
        g_cm2[j] = sum;
    } else if (t < 20672) {
        int j = t - 20608;
        float sum = u_c1[j];
        for (int k = 0; k < DF + HF; k++) {
            float s = u_g1[k] * rsqrtf(u_v1[k] + BN_EPS);
            sum += (u_b1[k] - u_mu1[k] * s) * u_W1[k * HF + j];
        }
        g_cu1[j] = sum;
    } else if (t < 20736) {
        int j = t - 20672;
        float sum = u_c2[j];
        for (int k = 0; k < HF; k++) {
            float s = u_g2[k] * rsqrtf(u_v2[k] + BN_EPS);
            sum += (u_b2[k] - u_mu2[k] * s) * u_W2[k * HF + j];
        }
        g_cu2[j] = sum;
    }
}

// ---------------- pack kernel: tf32 hi/lo split of all 6 matrices ----------------
// segments: [0,2048) m1 | [2048,4096) m2 | [4096,6144) e1 | [6144,8192) e2 |
//           [8192,10240) u2 | [10240,14336) u1 (K=128)
__global__ void pack_kernel(const float* __restrict__ We1, const float* __restrict__ We2) {
    int t = blockIdx.x * blockDim.x + threadIdx.x;
    const float* W; float4* P; int i;
    if (t < 2048)       { W = g_Wm1; P = g_Wm1p; i = t; }
    else if (t < 4096)  { W = g_Wm2; P = g_Wm2p; i = t - 2048; }
    else if (t < 6144)  { W = We1;   P = g_We1p; i = t - 4096; }
    else if (t < 8192)  { W = We2;   P = g_We2p; i = t - 6144; }
    else if (t < 10240) { W = g_Wu2; P = g_Wu2p; i = t - 8192; }
    else if (t < 14336) { W = g_Wu1; P = g_Wu1p; i = t - 10240; }
    else return;
    int kt = i >> 8, rem = i & 255, n = rem >> 2, r = rem & 3;
    float w1 = W[(kt * 8 + r) * 64 + n];
    float w2 = W[(kt * 8 + r + 4) * 64 + n];
    unsigned h1 = tf32r(w1), h2 = tf32r(w2);
    float4 o;
    o.x = __uint_as_float(h1);
    o.y = __uint_as_float(h2);
    o.z = __uint_as_float(tf32r(w1 - __uint_as_float(h1)));
    o.w = __uint_as_float(tf32r(w2 - __uint_as_float(h2)));
    P[i] = o;
}

// ---------------- zero accumulators ----------------
__global__ void zero_kernel() {
    size_t total = (size_t)NODES * HF;
    for (size_t i = blockIdx.x * (size_t)blockDim.x + threadIdx.x;
         i < total; i += (size_t)gridDim.x * blockDim.x) {
        g_agg[i] = 0.0f;
        if (i < NODES) g_cnt[i] = 0.0f;
    }
}

// =====================================================================
// msg kernel: per-node message MLP via tf32 mma
// smem floats: Wm1p 8192 | Wm2p 8192 | sb 128 | sA 8704 -> 25216 (~98.5KB)
// =====================================================================
#define MS_W2 8192
#define MS_B  16384
#define MS_A  16512
#define MS_TOT (16512 + 128 * ROWP)

__global__ void __launch_bounds__(256, 2)
msg_kernel(const float* __restrict__ nf, int N)
{
    extern __shared__ float sm[];
    float* sW1 = sm;
    float* sW2 = sm + MS_W2;
    float* sb  = sm + MS_B;
    float* sA  = sm + MS_A;

    int t = threadIdx.x;
    int w = t >> 5, l = t & 31;
    int lr = l >> 2, lc = l & 3;
    unsigned sbase = (unsigned)__cvta_generic_to_shared(sm);
    int n0 = blockIdx.x << 7;
    int nvalid = min(128, N - n0);

    for (int i = t; i < 2048; i += 256) {
        int r = i >> 4, q = i & 15;
        int rr = min(r, nvalid - 1);
        cp_async16(sbase + (MS_A + r * ROWP + q * 4) * 4,
                   nf + (size_t)(n0 + rr) * 64 + q * 4);
    }
    asm volatile("cp.async.commit_group;" ::: "memory");

    for (int i = t; i < 2048; i += 256) {
        ((float4*)sW1)[i] = g_Wm1p[i];
        ((float4*)sW2)[i] = g_Wm2p[i];
    }
    if (t < 64) {
        sb[t]      = g_cm1[t];
        sb[64 + t] = g_cm2[t];
    }
    asm volatile("cp.async.wait_group 0;" ::: "memory");
    __syncthreads();

    float* As = sA + w * 16 * ROWP;
    float acc[8][4];

    // GEMM1 in place
    wgemm16<8, ROWP>(As, (const float4*)sW1, sb, lr, lc, acc);
#pragma unroll
    for (int nt = 0; nt < 8; nt++) {
        float2 p0, p1;
        p0.x = gelu_f(acc[nt][0]); p0.y = gelu_f(acc[nt][1]);
        p1.x = gelu_f(acc[nt][2]); p1.y = gelu_f(acc[nt][3]);
        *(float2*)(As + lr * ROWP + nt * 8 + 2 * lc) = p0;
        *(float2*)(As + (lr + 8) * ROWP + nt * 8 + 2 * lc) = p1;
    }
    // GEMM2 -> g_msg
    wgemm16<8, ROWP>(As, (const float4*)sW2, sb + 64, lr, lc, acc);
    int n1 = n0 + w * 16 + lr;
    int n2 = n1 + 8;
    bool v1 = n1 < N, v2 = n2 < N;
#pragma unroll
    for (int nt = 0; nt < 8; nt++) {
        int col = nt * 8 + 2 * lc;
        if (v1) {
            float2 o; o.x = gelu_f(acc[nt][0]); o.y = gelu_f(acc[nt][1]);
            *(float2*)(g_msg + (size_t)n1 * 64 + col) = o;
        }
        if (v2) {
            float2 o; o.x = gelu_f(acc[nt][2]); o.y = gelu_f(acc[nt][3]);
            *(float2*)(g_msg + (size_t)n2 * 64 + col) = o;
        }
    }
}

// =====================================================================
// Edge kernel: tf32 2-pass edge MLP + gate + scatter, persistent + prefetch
// smem floats: We1p 8192 | We2p 8192 | sb 128 | sA 8704 -> 25216 (~98.5KB)
// =====================================================================
#define ESM_W2 8192
#define ESM_B  16384
#define ESM_A  16512
#define ESM_TOT (16512 + 128 * ROWP)

__global__ void __launch_bounds__(256, 2)
edge_kernel(const float* __restrict__ ef,
            const int* __restrict__ src, const int* __restrict__ dst,
            const float* __restrict__ ce1, const float* __restrict__ ce2,
            int E)
{
    extern __shared__ float sm[];
    float* sW1 = sm;
    float* sW2 = sm + ESM_W2;
    float* sb  = sm + ESM_B;
    float* sA  = sm + ESM_A;

    int t = threadIdx.x;
    int w = t >> 5, l = t & 31;
    int lr = l >> 2, lc = l & 3;
    unsigned sbase = (unsigned)__cvta_generic_to_shared(sm);
    int ntiles = (E + 127) >> 7;

    if (blockIdx.x < ntiles) {
        int e0 = blockIdx.x << 7;
        for (int i = t; i < 2048; i += 256) {
            int e = i >> 4, q = i & 15;
            int ee = min(e0 + e, E - 1);
            cp_async16(sbase + (ESM_A + e * ROWP + q * 4) * 4,
                       ef + (size_t)ee * 64 + q * 4);
        }
    }
    asm volatile("cp.async.commit_group;" ::: "memory");

    for (int i = t; i < 2048; i += 256) {
        ((float4*)sW1)[i] = g_We1p[i];
        ((float4*)sW2)[i] = g_We2p[i];
    }
    if (t < 64) {
        sb[t]      = __ldg(ce1 + t);
        sb[64 + t] = __ldg(ce2 + t);
    }

    float* As = sA + w * 16 * ROWP;

    for (int tile = blockIdx.x; tile < ntiles; tile += gridDim.x) {
        asm volatile("cp.async.wait_group 0;" ::: "memory");
        __syncthreads();
        int e0 = tile << 7;

        float acc[8][4];

        // GEMM1: er1 = gelu(ef @ We1 + c1), in place
        wgemm16<8, ROWP>(As, (const float4*)sW1, sb, lr, lc, acc);
#pragma unroll
        for (int nt = 0; nt < 8; nt++) {
            float2 p0, p1;
            p0.x = gelu_f(acc[nt][0]); p0.y = gelu_f(acc[nt][1]);
            p1.x = gelu_f(acc[nt][2]); p1.y = gelu_f(acc[nt][3]);
            *(float2*)(As + lr * ROWP + nt * 8 + 2 * lc) = p0;
            *(float2*)(As + (lr + 8) * ROWP + nt * 8 + 2 * lc) = p1;
        }

        // GEMM2: er2 = er1 @ We2 + c2; gate + scatter
        wgemm16<8, ROWP>(As, (const float4*)sW2, sb + 64, lr, lc, acc);

        int el1 = e0 + w * 16 + lr;
        int el2 = el1 + 8;
        bool v1 = el1 < E, v2 = el2 < E;
        int s1 = 0, d1 = 0, s2 = 0, d2 = 0;
        if (v1) { s1 = __ldg(src + el1); d1 = __ldg(dst + el1); }
        if (v2) { s2 = __ldg(src + el2); d2 = __ldg(dst + el2); }
#pragma unroll
        for (int nt = 0; nt < 8; nt++) {
            int col = nt * 8 + 2 * lc;
            if (v1) {
                float g0 = gelu_f(acc[nt][0]), g1 = gelu_f(acc[nt][1]);
                float2 m = __ldg((const float2*)(g_msg + (size_t)d1 * 64 + col));
                red_add_v2(g_agg + (size_t)s1 * 64 + col, m.x * g0, m.y * g1);
            }
            if (v2) {
                float g2 = gelu_f(acc[nt][2]), g3 = gelu_f(acc[nt][3]);
                float2 m = __ldg((const float2*)(g_msg + (size_t)d2 * 64 + col));
                red_add_v2(g_agg + (size_t)s2 * 64 + col, m.x * g2, m.y * g3);
            }
        }
        if (t < 128) {
            int e = e0 + t;
            if (e < E) atomicAdd(&g_cnt[__ldg(src + e)], 1.0f);
        }

        __syncthreads();   // all reads of sA done before restage

        int nxt = tile + gridDim.x;
        if (nxt < ntiles) {
            int ne0 = nxt << 7;
            for (int i = t; i < 2048; i += 256) {
                int e = i >> 4, q = i & 15;
                int ee = min(ne0 + e, E - 1);
                cp_async16(sbase + (ESM_A + e * ROWP + q * 4) * 4,
                           ef + (size_t)ee * 64 + q * 4);
            }
        }
        asm volatile("cp.async.commit_group;" ::: "memory");
    }
}

// =====================================================================
// node kernel: mean + update MLP via tf32 mma
// smem floats: Wu1p 16384 | Wu2p 8192 | sb 128 | sInv 128 | sA 128*132=16896
//   -> 41728 (~163KB), 1 block/SM
// =====================================================================
#define ND_W2  16384
#define ND_B   24576
#define ND_INV 24704
#define ND_A   24832
#define ND_TOT (24832 + 128 * ROWP2)

__global__ void __launch_bounds__(256, 1)
node_kernel(const float* __restrict__ nf, float* __restrict__ out, int N)
{
    extern __shared__ float sm[];
    float* sW1  = sm;
    float* sW2  = sm + ND_W2;
    float* sb   = sm + ND_B;
    float* sInv = sm + ND_INV;
    float* sA   = sm + ND_A;

    int t = threadIdx.x;
    int w = t >> 5, l = t & 31;
    int lr = l >> 2, lc = l & 3;
    unsigned sbase = (unsigned)__cvta_generic_to_shared(sm);
    int n0 = blockIdx.x << 7;
    int nvalid = min(128, N - n0);

    // stage nf -> cols 0-63, agg -> cols 64-127
    for (int i = t; i < 2048; i += 256) {
        int r = i >> 4, q = i & 15;
        int rr = min(r, nvalid - 1);
        cp_async16(sbase + (ND_A + r * ROWP2 + q * 4) * 4,
                   nf + (size_t)(n0 + rr) * 64 + q * 4);
        cp_async16(sbase + (ND_A + r * ROWP2 + 64 + q * 4) * 4,
                   g_agg + (size_t)(n0 + rr) * 64 + q * 4);
    }
    asm volatile("cp.async.commit_group;" ::: "memory");

    for (int i = t; i < 4096; i += 256) ((float4*)sW1)[i] = g_Wu1p[i];
    for (int i = t; i < 2048; i += 256) ((float4*)sW2)[i] = g_Wu2p[i];
    if (t < 64) {
        sb[t]      = g_cu1[t];
        sb[64 + t] = g_cu2[t];
    }
    if (t < 128) {
        int rr = min(t, nvalid - 1);
        sInv[t] = 1.0f / fmaxf(g_cnt[n0 + rr], 1.0f);
    }
    asm volatile("cp.async.wait_group 0;" ::: "memory");
    __syncthreads();

    // mean: scale agg columns
    for (int i = t; i < 8192; i += 256) {
        int r = i >> 6, c = i & 63;
        sA[r * ROWP2 + 64 + c] *= sInv[r];
    }
    __syncthreads();

    float* As = sA + w * 16 * ROWP2;
    float acc[8][4];

    // GEMM1: 128 -> 64, in place (warp-local rows)
    wgemm16<16, ROWP2>(As, (const float4*)sW1, sb, lr, lc, acc);
#pragma unroll
    for (int nt = 0; nt < 8; nt++) {
        float2 p0, p1;
        p0.x = gelu_f(acc[nt][0]); p0.y = gelu_f(acc[nt][1]);
        p1.x = gelu_f(acc[nt][2]); p1.y = gelu_f(acc[nt][3]);
        *(float2*)(As + lr * ROWP2 + nt * 8 + 2 * lc) = p0;
        *(float2*)(As + (lr + 8) * ROWP2 + nt * 8 + 2 * lc) = p1;
    }
    // GEMM2: 64 -> 64 -> out
    wgemm16<8, ROWP2>(As, (const float4*)sW2, sb + 64, lr, lc, acc);
    int n1 = n0 + w * 16 + lr;
    int n2 = n1 + 8;
    bool v1 = n1 < N, v2 = n2 < N;
#pragma unroll
    for (int nt = 0; nt < 8; nt++) {
        int col = nt * 8 + 2 * lc;
        if (v1) {
            float2 o; o.x = gelu_f(acc[nt][0]); o.y = gelu_f(acc[nt][1]);
            *(float2*)(out + (size_t)n1 * 64 + col) = o;
        }
        if (v2) {
            float2 o; o.x = gelu_f(acc[nt][2]); o.y = gelu_f(acc[nt][3]);
            *(float2*)(out + (size_t)n2 * 64 + col) = o;
        }
    }
}

// ---------------- launch ----------------
extern "C" void kernel_launch(void* const* d_in, const int* in_sizes, int n_in,
                              void* d_out, int out_size)
{
    bool dictOrder = (in_sizes[2] > 64);
    const float* nf = (const float*)d_in[0];
    const float* ef = (const float*)d_in[1];
    const int* src = (const int*)d_in[dictOrder ? 2 : 30];
    const int* dst = (const int*)d_in[dictOrder ? 3 : 31];
    int p0 = dictOrder ? 4 : 2;
    const float* P[28];
    for (int i = 0; i < 28; i++) P[i] = (const float*)d_in[p0 + i];

    int E = in_sizes[1] / 64;
    int N = in_sizes[0] / 64;

    cudaFuncSetAttribute(msg_kernel, cudaFuncAttributeMaxDynamicSharedMemorySize,
                         MS_TOT * (int)sizeof(float));
    cudaFuncSetAttribute(edge_kernel, cudaFuncAttributeMaxDynamicSharedMemorySize,
                         ESM_TOT * (int)sizeof(float));
    cudaFuncSetAttribute(node_kernel, cudaFuncAttributeMaxDynamicSharedMemorySize,
                         ND_TOT * (int)sizeof(float));

    fold_kernel<<<(20736 + 255) / 256, 256>>>(
        P[0], P[1], P[2], P[3], P[4], P[5], P[6], P[7], P[8], P[9], P[10], P[11],
        P[16], P[17], P[18], P[19], P[20], P[21], P[22], P[23], P[24], P[25], P[26], P[27]);
    pack_kernel<<<56, 256>>>(P[12], P[14]);
    zero_kernel<<<2048, 256>>>();
    msg_kernel<<<(N + 127) / 128, 256, MS_TOT * sizeof(float)>>>(nf, N);
    edge_kernel<<<296, 256, ESM_TOT * sizeof(float)>>>(
        ef, src, dst, P[13], P[15], E);
    node_kernel<<<(N + 127) / 128, 256, ND_TOT * sizeof(float)>>>(
        nf, (float*)d_out, N);
}